// round 4
// baseline (speedup 1.0000x reference)
#include <cuda_runtime.h>
#include <cstdint>

#define BATCH   2
#define SEQ     2048
#define HIDDEN  1024
#define NHEADS  16
#define HDIM    64
#define MTOT    (BATCH*SEQ)

// ---------------- scratch ----------------
__device__ float g_Q[MTOT * HIDDEN];   // [B*S, 1024]
__device__ float g_K[MTOT * HDIM];     // [B*S, 64]
__device__ float g_V[MTOT * HDIM];     // [B*S, 64]
__device__ float g_A[MTOT * HIDDEN];   // attention out [B*S, H*D]

// ---------------- helpers ----------------
__device__ __forceinline__ uint32_t f2t(float f) {
    uint32_t r;
    asm("cvt.rna.tf32.f32 %0, %1;" : "=r"(r) : "f"(f));
    return r;
}
__device__ __forceinline__ void mma8(float* c, const uint32_t* a, const uint32_t* b) {
    asm volatile(
        "mma.sync.aligned.m16n8k8.row.col.f32.tf32.tf32.f32 "
        "{%0,%1,%2,%3},{%4,%5,%6,%7},{%8,%9},{%0,%1,%2,%3};"
        : "+f"(c[0]), "+f"(c[1]), "+f"(c[2]), "+f"(c[3])
        : "r"(a[0]), "r"(a[1]), "r"(a[2]), "r"(a[3]), "r"(b[0]), "r"(b[1]));
}

// ============ GEMM: C[M,*] = A[M,1024] @ W[1024,N] + bias (tf32 mma) =========
// (unchanged from round 3 — 81us/launch; next optimization target)
#define G_AS   0
#define G_WS   8704            // 128*68
#define G_BIAS (8704 + 8704)   // + 64*136
#define G_SMEM ((G_BIAS + 128) * 4)

__global__ __launch_bounds__(256)
void gemm_mma(const float* __restrict__ A, const float* __restrict__ W,
              const float* __restrict__ bias, float* __restrict__ C,
              const float* __restrict__ Wk, const float* __restrict__ bk,
              const float* __restrict__ Wv, const float* __restrict__ bv,
              int kv_tile)
{
    extern __shared__ uint32_t sm[];
    uint32_t* As = sm + G_AS;
    uint32_t* Ws = sm + G_WS;
    float* Bias  = (float*)(sm + G_BIAS);

    const int tid = threadIdx.x, lane = tid & 31, wid = tid >> 5;
    const int g = lane >> 2, k4 = lane & 3;
    const int wr = wid >> 2, wc = wid & 3;
    const int m0 = blockIdx.y * 128;
    const bool kvm = ((int)blockIdx.x == kv_tile);
    const int n0 = blockIdx.x * 128;

    if (tid < 128)
        Bias[tid] = kvm ? (tid < 64 ? bk[tid] : bv[tid - 64]) : bias[n0 + tid];

    float acc[4][4][4] = {};

    for (int kc = 0; kc < 16; ++kc) {
        const int k0 = kc * 64;
#pragma unroll
        for (int l = 0; l < 8; l++) {
            int idx = tid + l * 256;
            int r = idx >> 4, c4 = idx & 15;
            float4 v = *(const float4*)(A + (size_t)(m0 + r) * HIDDEN + k0 + c4 * 4);
            uint32_t* d = &As[r * 68 + c4 * 4];
            d[0] = f2t(v.x); d[1] = f2t(v.y); d[2] = f2t(v.z); d[3] = f2t(v.w);
        }
        if (!kvm) {
#pragma unroll
            for (int l = 0; l < 8; l++) {
                int idx = tid + l * 256;
                int r = idx >> 5, c4 = idx & 31;
                float4 v = *(const float4*)(W + (size_t)(k0 + r) * HIDDEN + n0 + c4 * 4);
                uint32_t* d = &Ws[r * 136 + c4 * 4];
                d[0] = f2t(v.x); d[1] = f2t(v.y); d[2] = f2t(v.z); d[3] = f2t(v.w);
            }
        } else {
#pragma unroll
            for (int l = 0; l < 32; l++) {
                int idx = tid + l * 256;
                int r = idx >> 7, c = idx & 127;
                float v = (c < 64) ? Wk[(size_t)(k0 + r) * HDIM + c]
                                   : Wv[(size_t)(k0 + r) * HDIM + c - 64];
                Ws[r * 136 + c] = f2t(v);
            }
        }
        __syncthreads();

#pragma unroll
        for (int ks = 0; ks < 8; ++ks) {
            uint32_t a[4][4], b[4][2];
#pragma unroll
            for (int mt = 0; mt < 4; mt++) {
                const uint32_t* p = &As[(wr * 64 + mt * 16 + g) * 68 + ks * 8 + k4];
                a[mt][0] = p[0]; a[mt][1] = p[8 * 68];
                a[mt][2] = p[4]; a[mt][3] = p[8 * 68 + 4];
            }
#pragma unroll
            for (int nt = 0; nt < 4; nt++) {
                int c = wc * 32 + nt * 8 + g;
                b[nt][0] = Ws[(ks * 8 + k4) * 136 + c];
                b[nt][1] = Ws[(ks * 8 + 4 + k4) * 136 + c];
            }
#pragma unroll
            for (int mt = 0; mt < 4; mt++)
#pragma unroll
                for (int nt = 0; nt < 4; nt++)
                    mma8(acc[mt][nt], a[mt], b[nt]);
        }
        __syncthreads();
    }

#pragma unroll
    for (int mt = 0; mt < 4; mt++) {
        int r = m0 + wr * 64 + mt * 16 + g;
#pragma unroll
        for (int nt = 0; nt < 4; nt++) {
            int c = wc * 32 + nt * 8 + 2 * k4;
            float2 v0 = { acc[mt][nt][0] + Bias[c], acc[mt][nt][1] + Bias[c + 1] };
            float2 v1 = { acc[mt][nt][2] + Bias[c], acc[mt][nt][3] + Bias[c + 1] };
            if (!kvm) {
                *(float2*)(C + (size_t)r * HIDDEN + n0 + c) = v0;
                *(float2*)(C + (size_t)(r + 8) * HIDDEN + n0 + c) = v1;
            } else if (c < 64) {
                *(float2*)(g_K + (size_t)r * HDIM + c) = v0;
                *(float2*)(g_K + (size_t)(r + 8) * HDIM + c) = v1;
            } else {
                *(float2*)(g_V + (size_t)r * HDIM + c - 64) = v0;
                *(float2*)(g_V + (size_t)(r + 8) * HDIM + c - 64) = v1;
            }
        }
    }
}

// ============ attention: register-resident P, warp = m16 slab ================
// CTA = 64 q-rows (4 warps x 16 rows), one head, one batch; 16 key tiles of 128.
// S warp tile 16x128 (sacc[16][4]); P stays in those regs (tf32 bits);
// PV A-fragments built via quad shuffles; O warp tile 16x64 (oacc[8][4]).
#define ATT_KS 0
#define ATT_VS 8704               // 128*68
#define ATT_MB (8704 + 8448)     // + 128*66
#define ATT_SMEM ((ATT_MB + 4) * 4)

__global__ __launch_bounds__(128, 3)
void attn_mma(const int* __restrict__ mask)
{
    extern __shared__ uint32_t sm[];
    uint32_t* Ks = sm + ATT_KS;   // [128][68]
    uint32_t* Vs = sm + ATT_VS;   // [128][66]
    uint32_t* Mb = sm + ATT_MB;   // 4 mask bitmask words

    const int tid = threadIdx.x, lane = tid & 31, wid = tid >> 5;
    const int g = lane >> 2, k4 = lane & 3;
    const int qt = blockIdx.x, h = blockIdx.y, b = blockIdx.z;
    const int qrow0 = qt * 64 + wid * 16;

    // Q fragments in registers (once), pre-scaled by 1/sqrt(64)
    uint32_t qf[8][4];
    {
        const float* Qb = g_Q + ((size_t)(b * SEQ + qrow0)) * HIDDEN + h * HDIM;
#pragma unroll
        for (int ks = 0; ks < 8; ks++) {
            qf[ks][0] = f2t(Qb[(size_t)g * HIDDEN + ks * 8 + k4] * 0.125f);
            qf[ks][1] = f2t(Qb[(size_t)(g + 8) * HIDDEN + ks * 8 + k4] * 0.125f);
            qf[ks][2] = f2t(Qb[(size_t)g * HIDDEN + ks * 8 + k4 + 4] * 0.125f);
            qf[ks][3] = f2t(Qb[(size_t)(g + 8) * HIDDEN + ks * 8 + k4 + 4] * 0.125f);
        }
    }

    float oacc[8][4] = {};
    float sum0 = 0.f, sum1 = 0.f;

    const float* Kb = g_K + (size_t)b * SEQ * HDIM;
    const float* Vb = g_V + (size_t)b * SEQ * HDIM;
    const int*   Mk = mask + (size_t)b * SEQ;

    for (int kt = 0; kt < 16; ++kt) {
        // ---- load K/V tiles (128 keys x 64 dims) + mask bits ----
#pragma unroll
        for (int l = 0; l < 16; l++) {
            int idx = tid + l * 128;
            int r = idx >> 4, c4 = idx & 15;
            float4 kv = *(const float4*)(Kb + (size_t)(kt * 128 + r) * HDIM + c4 * 4);
            uint32_t* dk = &Ks[r * 68 + c4 * 4];
            dk[0] = f2t(kv.x); dk[1] = f2t(kv.y); dk[2] = f2t(kv.z); dk[3] = f2t(kv.w);
            float4 vv = *(const float4*)(Vb + (size_t)(kt * 128 + r) * HDIM + c4 * 4);
            uint32_t* dv = &Vs[r * 66 + c4 * 4];
            dv[0] = f2t(vv.x); dv[1] = f2t(vv.y); dv[2] = f2t(vv.z); dv[3] = f2t(vv.w);
        }
        {
            uint32_t bits = __ballot_sync(0xffffffffu, Mk[kt * 128 + wid * 32 + lane] != 0);
            if (lane == 0) Mb[wid] = bits;
        }
        __syncthreads();

        uint32_t mreg[4] = { Mb[0], Mb[1], Mb[2], Mb[3] };

        // ---- S = Q @ K^T : warp tile 16 x 128 ----
        float sacc[16][4] = {};
#pragma unroll
        for (int ks = 0; ks < 8; ++ks) {
#pragma unroll
            for (int nb = 0; nb < 16; nb++) {
                const uint32_t* kp = &Ks[(nb * 8 + g) * 68 + ks * 8 + k4];
                uint32_t bb[2] = { kp[0], kp[4] };
                mma8(sacc[nb], qf[ks], bb);
            }
        }

        // ---- P = exp(S) masked, accumulate row sums, tf32 in place ----
#pragma unroll
        for (int nb = 0; nb < 16; nb++) {
            int c = nb * 8 + 2 * k4;
            bool m0 = (mreg[c >> 5] >> (c & 31)) & 1;
            bool m1 = (mreg[(c + 1) >> 5] >> ((c + 1) & 31)) & 1;
            float p00 = m0 ? __expf(sacc[nb][0]) : 0.f;
            float p01 = m1 ? __expf(sacc[nb][1]) : 0.f;
            float p10 = m0 ? __expf(sacc[nb][2]) : 0.f;
            float p11 = m1 ? __expf(sacc[nb][3]) : 0.f;
            sum0 += p00 + p01;
            sum1 += p10 + p11;
            sacc[nb][0] = __uint_as_float(f2t(p00));
            sacc[nb][1] = __uint_as_float(f2t(p01));
            sacc[nb][2] = __uint_as_float(f2t(p10));
            sacc[nb][3] = __uint_as_float(f2t(p11));
        }

        // ---- O += P @ V : A-frags from sacc via quad shuffles ----
        const int src_lo = (lane & ~3) + (k4 >> 1);
        const int src_hi = src_lo + 2;
        const bool odd = (k4 & 1);
#pragma unroll
        for (int ks = 0; ks < 16; ++ks) {
            uint32_t s0 = __float_as_uint(sacc[ks][0]);
            uint32_t s1 = __float_as_uint(sacc[ks][1]);
            uint32_t s2 = __float_as_uint(sacc[ks][2]);
            uint32_t s3 = __float_as_uint(sacc[ks][3]);
            uint32_t x0 = __shfl_sync(0xffffffffu, s0, src_lo);
            uint32_t x1 = __shfl_sync(0xffffffffu, s1, src_lo);
            uint32_t y0 = __shfl_sync(0xffffffffu, s2, src_lo);
            uint32_t y1 = __shfl_sync(0xffffffffu, s3, src_lo);
            uint32_t z0 = __shfl_sync(0xffffffffu, s0, src_hi);
            uint32_t z1 = __shfl_sync(0xffffffffu, s1, src_hi);
            uint32_t w0 = __shfl_sync(0xffffffffu, s2, src_hi);
            uint32_t w1 = __shfl_sync(0xffffffffu, s3, src_hi);
            uint32_t a[4];
            a[0] = odd ? x1 : x0;   // (g,    ks*8+k4)
            a[1] = odd ? y1 : y0;   // (g+8,  ks*8+k4)
            a[2] = odd ? z1 : z0;   // (g,    ks*8+k4+4)
            a[3] = odd ? w1 : w0;   // (g+8,  ks*8+k4+4)
#pragma unroll
            for (int nb = 0; nb < 8; nb++) {
                uint32_t bb[2] = { Vs[(ks * 8 + k4) * 66 + nb * 8 + g],
                                   Vs[(ks * 8 + 4 + k4) * 66 + nb * 8 + g] };
                mma8(oacc[nb], a, bb);
            }
        }
        __syncthreads();
    }

    // ---- row-sum quad reduction (warp-private rows; no atomics) ----
    sum0 += __shfl_xor_sync(0xffffffffu, sum0, 1);
    sum0 += __shfl_xor_sync(0xffffffffu, sum0, 2);
    sum1 += __shfl_xor_sync(0xffffffffu, sum1, 1);
    sum1 += __shfl_xor_sync(0xffffffffu, sum1, 2);
    const float inv0 = 1.f / sum0;
    const float inv1 = 1.f / sum1;

    // ---- normalize + store ----
    float* Ob = g_A + ((size_t)(b * SEQ + qrow0 + g)) * HIDDEN + h * HDIM;
#pragma unroll
    for (int nb = 0; nb < 8; nb++) {
        int c = nb * 8 + 2 * k4;
        float2 v0 = { oacc[nb][0] * inv0, oacc[nb][1] * inv0 };
        float2 v1 = { oacc[nb][2] * inv1, oacc[nb][3] * inv1 };
        *(float2*)(Ob + c) = v0;
        *(float2*)(Ob + (size_t)8 * HIDDEN + c) = v1;
    }
}

// ---------------- launch --------------------------------------------------
extern "C" void kernel_launch(void* const* d_in, const int* in_sizes, int n_in,
                              void* d_out, int out_size)
{
    const float* X    = (const float*)d_in[0];
    const float* Wq   = (const float*)d_in[1];
    const float* bq   = (const float*)d_in[2];
    const float* Wk   = (const float*)d_in[3];
    const float* bk   = (const float*)d_in[4];
    const float* Wv   = (const float*)d_in[5];
    const float* bv   = (const float*)d_in[6];
    const float* Wo   = (const float*)d_in[7];
    const float* bo   = (const float*)d_in[8];
    const int*   mask = (const int*)d_in[9];
    float* out = (float*)d_out;

    float *qp = nullptr, *ap = nullptr;
    cudaGetSymbolAddress((void**)&qp, g_Q);
    cudaGetSymbolAddress((void**)&ap, g_A);

    cudaFuncSetAttribute(gemm_mma, cudaFuncAttributeMaxDynamicSharedMemorySize, G_SMEM);
    cudaFuncSetAttribute(attn_mma, cudaFuncAttributeMaxDynamicSharedMemorySize, ATT_SMEM);

    // 1) QKV: 8 Q col-tiles + 1 combined [K|V] tile
    dim3 g1(9, MTOT / 128);
    gemm_mma<<<g1, 256, G_SMEM>>>(X, Wq, bq, qp, Wk, bk, Wv, bv, 8);

    // 2) attention: CTA = 64 q-rows
    dim3 g2(SEQ / 64, NHEADS, BATCH);
    attn_mma<<<g2, 128, ATT_SMEM>>>(mask);

    // 3) O projection -> d_out
    dim3 g3(HIDDEN / 128, MTOT / 128);
    gemm_mma<<<g3, 256, G_SMEM>>>(ap, Wo, bo, out, nullptr, nullptr, nullptr, nullptr, -1);
}

// round 5
// speedup vs baseline: 1.6523x; 1.6523x over previous
#include <cuda_runtime.h>
#include <cuda_fp16.h>
#include <cstdint>

#define BATCH   2
#define SEQ     2048
#define HIDDEN  1024
#define NHEADS  16
#define HDIM    64
#define MTOT    (BATCH*SEQ)

// ---------------- scratch ----------------
__device__ float g_Q[MTOT * HIDDEN];   // [B*S, 1024]
__device__ float g_K[MTOT * HDIM];     // [B*S, 64]
__device__ float g_V[MTOT * HDIM];     // [B*S, 64]
__device__ float g_A[MTOT * HIDDEN];   // attention out [B*S, H*D]

// ---------------- helpers ----------------
__device__ __forceinline__ uint32_t smem_u32(const void* p) {
    uint32_t a;
    asm("{ .reg .u64 t; cvta.to.shared.u64 t, %1; cvt.u32.u64 %0, t; }" : "=r"(a) : "l"(p));
    return a;
}
__device__ __forceinline__ uint32_t f2t(float f) {
    uint32_t r;
    asm("cvt.rna.tf32.f32 %0, %1;" : "=r"(r) : "f"(f));
    return r;
}
__device__ __forceinline__ void mma8(float* c, const uint32_t* a, const uint32_t* b) {
    asm volatile(
        "mma.sync.aligned.m16n8k8.row.col.f32.tf32.tf32.f32 "
        "{%0,%1,%2,%3},{%4,%5,%6,%7},{%8,%9},{%0,%1,%2,%3};"
        : "+f"(c[0]), "+f"(c[1]), "+f"(c[2]), "+f"(c[3])
        : "r"(a[0]), "r"(a[1]), "r"(a[2]), "r"(a[3]), "r"(b[0]), "r"(b[1]));
}
__device__ __forceinline__ void mma16(float* c, const uint32_t* a, const uint32_t* b) {
    asm volatile(
        "mma.sync.aligned.m16n8k16.row.col.f32.f16.f16.f32 "
        "{%0,%1,%2,%3},{%4,%5,%6,%7},{%8,%9},{%0,%1,%2,%3};"
        : "+f"(c[0]), "+f"(c[1]), "+f"(c[2]), "+f"(c[3])
        : "r"(a[0]), "r"(a[1]), "r"(a[2]), "r"(a[3]), "r"(b[0]), "r"(b[1]));
}
__device__ __forceinline__ void ldm_x4(uint32_t* r, uint32_t a) {
    asm volatile("ldmatrix.sync.aligned.m8n8.x4.shared.b16 {%0,%1,%2,%3}, [%4];"
        : "=r"(r[0]), "=r"(r[1]), "=r"(r[2]), "=r"(r[3]) : "r"(a));
}
__device__ __forceinline__ void ldm_x2(uint32_t* r, uint32_t a) {
    asm volatile("ldmatrix.sync.aligned.m8n8.x2.shared.b16 {%0,%1}, [%2];"
        : "=r"(r[0]), "=r"(r[1]) : "r"(a));
}
__device__ __forceinline__ void ldm_x2t(uint32_t* r, uint32_t a) {
    asm volatile("ldmatrix.sync.aligned.m8n8.x2.trans.shared.b16 {%0,%1}, [%2];"
        : "=r"(r[0]), "=r"(r[1]) : "r"(a));
}
__device__ __forceinline__ uint32_t h2u(__half2 h) { return *(uint32_t*)&h; }

// ============ GEMM: C[M,*] = A[M,1024] @ W[1024,N] + bias (tf32 mma) =========
// Round-3 structure + register prefetch of next K-chunk (LDG overlaps mma).
#define G_AS   0
#define G_WS   8704            // 128*68
#define G_BIAS (8704 + 8704)   // + 64*136
#define G_SMEM ((G_BIAS + 128) * 4)

__global__ __launch_bounds__(256)
void gemm_mma(const float* __restrict__ A, const float* __restrict__ W,
              const float* __restrict__ bias, float* __restrict__ C,
              const float* __restrict__ Wk, const float* __restrict__ bk,
              const float* __restrict__ Wv, const float* __restrict__ bv,
              int kv_tile)
{
    extern __shared__ uint32_t sm[];
    uint32_t* As = sm + G_AS;
    uint32_t* Ws = sm + G_WS;
    float* Bias  = (float*)(sm + G_BIAS);

    const int tid = threadIdx.x, lane = tid & 31, wid = tid >> 5;
    const int g = lane >> 2, k4 = lane & 3;
    const int wr = wid >> 2, wc = wid & 3;
    const int m0 = blockIdx.y * 128;
    const bool kvm = ((int)blockIdx.x == kv_tile);
    const int n0 = blockIdx.x * 128;

    if (tid < 128)
        Bias[tid] = kvm ? (tid < 64 ? bk[tid] : bv[tid - 64]) : bias[n0 + tid];

    float acc[4][4][4] = {};
    float4 stA[8];
    float4 stW[8];
    float  stK[32];

    // ---- prologue: load + store chunk 0 ----
#pragma unroll
    for (int l = 0; l < 8; l++) {
        int idx = tid + l * 256;
        int r = idx >> 4, c4 = idx & 15;
        stA[l] = *(const float4*)(A + (size_t)(m0 + r) * HIDDEN + c4 * 4);
    }
    if (!kvm) {
#pragma unroll
        for (int l = 0; l < 8; l++) {
            int idx = tid + l * 256;
            int r = idx >> 5, c4 = idx & 31;
            stW[l] = *(const float4*)(W + (size_t)r * HIDDEN + n0 + c4 * 4);
        }
    } else {
#pragma unroll
        for (int l = 0; l < 32; l++) {
            int idx = tid + l * 256;
            int r = idx >> 7, c = idx & 127;
            stK[l] = (c < 64) ? Wk[(size_t)r * HDIM + c] : Wv[(size_t)r * HDIM + c - 64];
        }
    }
#pragma unroll
    for (int l = 0; l < 8; l++) {
        int idx = tid + l * 256;
        int r = idx >> 4, c4 = idx & 15;
        uint32_t* d = &As[r * 68 + c4 * 4];
        d[0] = f2t(stA[l].x); d[1] = f2t(stA[l].y); d[2] = f2t(stA[l].z); d[3] = f2t(stA[l].w);
    }
    if (!kvm) {
#pragma unroll
        for (int l = 0; l < 8; l++) {
            int idx = tid + l * 256;
            int r = idx >> 5, c4 = idx & 31;
            uint32_t* d = &Ws[r * 136 + c4 * 4];
            d[0] = f2t(stW[l].x); d[1] = f2t(stW[l].y); d[2] = f2t(stW[l].z); d[3] = f2t(stW[l].w);
        }
    } else {
#pragma unroll
        for (int l = 0; l < 32; l++) {
            int idx = tid + l * 256;
            int r = idx >> 7, c = idx & 127;
            Ws[r * 136 + c] = f2t(stK[l]);
        }
    }
    __syncthreads();

    for (int kc = 0; kc < 16; ++kc) {
        // prefetch next chunk into regs (overlaps the mma below)
        if (kc < 15) {
            const int k0 = (kc + 1) * 64;
#pragma unroll
            for (int l = 0; l < 8; l++) {
                int idx = tid + l * 256;
                int r = idx >> 4, c4 = idx & 15;
                stA[l] = *(const float4*)(A + (size_t)(m0 + r) * HIDDEN + k0 + c4 * 4);
            }
            if (!kvm) {
#pragma unroll
                for (int l = 0; l < 8; l++) {
                    int idx = tid + l * 256;
                    int r = idx >> 5, c4 = idx & 31;
                    stW[l] = *(const float4*)(W + (size_t)(k0 + r) * HIDDEN + n0 + c4 * 4);
                }
            } else {
#pragma unroll
                for (int l = 0; l < 32; l++) {
                    int idx = tid + l * 256;
                    int r = idx >> 7, c = idx & 127;
                    stK[l] = (c < 64) ? Wk[(size_t)(k0 + r) * HDIM + c]
                                      : Wv[(size_t)(k0 + r) * HDIM + c - 64];
                }
            }
        }

#pragma unroll
        for (int ks = 0; ks < 8; ++ks) {
            uint32_t a[4][4], b[4][2];
#pragma unroll
            for (int mt = 0; mt < 4; mt++) {
                const uint32_t* p = &As[(wr * 64 + mt * 16 + g) * 68 + ks * 8 + k4];
                a[mt][0] = p[0]; a[mt][1] = p[8 * 68];
                a[mt][2] = p[4]; a[mt][3] = p[8 * 68 + 4];
            }
#pragma unroll
            for (int nt = 0; nt < 4; nt++) {
                int c = wc * 32 + nt * 8 + g;
                b[nt][0] = Ws[(ks * 8 + k4) * 136 + c];
                b[nt][1] = Ws[(ks * 8 + 4 + k4) * 136 + c];
            }
#pragma unroll
            for (int mt = 0; mt < 4; mt++)
#pragma unroll
                for (int nt = 0; nt < 4; nt++)
                    mma8(acc[mt][nt], a[mt], b[nt]);
        }

        if (kc < 15) {
            __syncthreads();
#pragma unroll
            for (int l = 0; l < 8; l++) {
                int idx = tid + l * 256;
                int r = idx >> 4, c4 = idx & 15;
                uint32_t* d = &As[r * 68 + c4 * 4];
                d[0] = f2t(stA[l].x); d[1] = f2t(stA[l].y); d[2] = f2t(stA[l].z); d[3] = f2t(stA[l].w);
            }
            if (!kvm) {
#pragma unroll
                for (int l = 0; l < 8; l++) {
                    int idx = tid + l * 256;
                    int r = idx >> 5, c4 = idx & 31;
                    uint32_t* d = &Ws[r * 136 + c4 * 4];
                    d[0] = f2t(stW[l].x); d[1] = f2t(stW[l].y); d[2] = f2t(stW[l].z); d[3] = f2t(stW[l].w);
                }
            } else {
#pragma unroll
                for (int l = 0; l < 32; l++) {
                    int idx = tid + l * 256;
                    int r = idx >> 7, c = idx & 127;
                    Ws[r * 136 + c] = f2t(stK[l]);
                }
            }
            __syncthreads();
        }
    }

#pragma unroll
    for (int mt = 0; mt < 4; mt++) {
        int r = m0 + wr * 64 + mt * 16 + g;
#pragma unroll
        for (int nt = 0; nt < 4; nt++) {
            int c = wc * 32 + nt * 8 + 2 * k4;
            float2 v0 = { acc[mt][nt][0] + Bias[c], acc[mt][nt][1] + Bias[c + 1] };
            float2 v1 = { acc[mt][nt][2] + Bias[c], acc[mt][nt][3] + Bias[c + 1] };
            if (!kvm) {
                *(float2*)(C + (size_t)r * HIDDEN + n0 + c) = v0;
                *(float2*)(C + (size_t)(r + 8) * HIDDEN + n0 + c) = v1;
            } else if (c < 64) {
                *(float2*)(g_K + (size_t)r * HDIM + c) = v0;
                *(float2*)(g_K + (size_t)(r + 8) * HDIM + c) = v1;
            } else {
                *(float2*)(g_V + (size_t)r * HDIM + c - 64) = v0;
                *(float2*)(g_V + (size_t)(r + 8) * HDIM + c - 64) = v1;
            }
        }
    }
}

// ============ attention: fp16 mma + ldmatrix, no-rescale softmax =============
// CTA: 128 q-rows, 8 warps as 4x2 (rows 32/warp, keys 64 or dims 32 per warp).
// Half layouts: Qsh/Ksh/Vsh [128][72], Psh [128][136].
#define QSH_B 0
#define KSH_B 18432
#define VSH_B 36864
#define PSH_B 55296
#define MSK_B 90112
#define LS_B  90624
#define ATT_SMEM 91136

__global__ __launch_bounds__(256)
void attn_mma(const int* __restrict__ mask)
{
    extern __shared__ char smc[];
    const uint32_t sb = smem_u32(smc);
    __half* Qsh = (__half*)(smc + QSH_B);
    __half* Ksh = (__half*)(smc + KSH_B);
    __half* Vsh = (__half*)(smc + VSH_B);
    __half* Psh = (__half*)(smc + PSH_B);
    int*    Msk = (int*)(smc + MSK_B);
    float*  Ls  = (float*)(smc + LS_B);

    const int tid = threadIdx.x, lane = tid & 31, wid = tid >> 5;
    const int g = lane >> 2, k4 = lane & 3;
    const int wr = wid >> 1, wc = wid & 1;
    const int qt = blockIdx.x, h = blockIdx.y, b = blockIdx.z;

    // ---- Q tile (once), scaled by 1/sqrt(64), fp16 ----
    {
        const float* Qb = g_Q + ((size_t)(b * SEQ + qt * 128)) * HIDDEN + h * HDIM;
#pragma unroll
        for (int l = 0; l < 8; l++) {
            int idx = tid + l * 256;
            int r = idx >> 4, c4 = idx & 15;
            float4 v = *(const float4*)(Qb + (size_t)r * HIDDEN + c4 * 4);
            uint2 u;
            u.x = h2u(__floats2half2_rn(v.x * 0.125f, v.y * 0.125f));
            u.y = h2u(__floats2half2_rn(v.z * 0.125f, v.w * 0.125f));
            *(uint2*)&Qsh[r * 72 + c4 * 4] = u;
        }
    }
    if (tid < 128) Ls[tid] = 0.f;

    float oacc[2][4][4] = {};
    float part[2][2] = {};

    const float* Kb = g_K + (size_t)b * SEQ * HDIM;
    const float* Vb = g_V + (size_t)b * SEQ * HDIM;
    const int*   Mb = mask + (size_t)b * SEQ;

    for (int kt = 0; kt < 16; ++kt) {
        // ---- load K/V tiles (128 keys x 64 dims) as fp16 + mask ----
#pragma unroll
        for (int l = 0; l < 8; l++) {
            int idx = tid + l * 256;
            int r = idx >> 4, c4 = idx & 15;
            float4 kv = *(const float4*)(Kb + (size_t)(kt * 128 + r) * HDIM + c4 * 4);
            uint2 uk;
            uk.x = h2u(__floats2half2_rn(kv.x, kv.y));
            uk.y = h2u(__floats2half2_rn(kv.z, kv.w));
            *(uint2*)&Ksh[r * 72 + c4 * 4] = uk;
            float4 vv = *(const float4*)(Vb + (size_t)(kt * 128 + r) * HDIM + c4 * 4);
            uint2 uv;
            uv.x = h2u(__floats2half2_rn(vv.x, vv.y));
            uv.y = h2u(__floats2half2_rn(vv.z, vv.w));
            *(uint2*)&Vsh[r * 72 + c4 * 4] = uv;
        }
        if (tid < 128) Msk[tid] = Mb[kt * 128 + tid];
        __syncthreads();

        // ---- S = Q @ K^T ; warp tile 32 rows x 64 keys ----
#pragma unroll
        for (int mt = 0; mt < 2; ++mt) {
            const int arow = wr * 32 + mt * 16 + (lane & 15);
            const int acol = (lane >> 4) * 8;
            uint32_t qa[4][4];
#pragma unroll
            for (int ks = 0; ks < 4; ks++)
                ldm_x4(qa[ks], sb + QSH_B + (uint32_t)(arow * 72 + ks * 16 + acol) * 2);

            float sacc[8][4] = {};
            const int ln = lane & 15;
            const int krow_in = (ln & 7);
            const int kcol_in = (ln >> 3) * 8;
#pragma unroll
            for (int nt = 0; nt < 8; nt++) {
                const int krow = wc * 64 + nt * 8 + krow_in;
#pragma unroll
                for (int ks = 0; ks < 4; ks++) {
                    uint32_t bb[2];
                    ldm_x2(bb, sb + KSH_B + (uint32_t)(krow * 72 + ks * 16 + kcol_in) * 2);
                    mma16(sacc[nt], qa[ks], bb);
                }
            }

            // ---- P = exp(S) (masked); pack fp16 into Psh; row partials ----
            const int prow = wr * 32 + mt * 16 + g;
#pragma unroll
            for (int nt = 0; nt < 8; nt++) {
                int c = wc * 64 + nt * 8 + 2 * k4;
                bool m0 = Msk[c] != 0, m1 = Msk[c + 1] != 0;
                float p00 = m0 ? __expf(sacc[nt][0]) : 0.f;
                float p01 = m1 ? __expf(sacc[nt][1]) : 0.f;
                float p10 = m0 ? __expf(sacc[nt][2]) : 0.f;
                float p11 = m1 ? __expf(sacc[nt][3]) : 0.f;
                part[mt][0] += p00 + p01;
                part[mt][1] += p10 + p11;
                *(uint32_t*)&Psh[prow * 136 + c]       = h2u(__floats2half2_rn(p00, p01));
                *(uint32_t*)&Psh[(prow + 8) * 136 + c] = h2u(__floats2half2_rn(p10, p11));
            }
        }
        __syncthreads();

        // ---- O += P @ V ; warp tile 32 rows x 32 dims, K = 128 keys ----
#pragma unroll
        for (int mt = 0; mt < 2; ++mt) {
            const int arow = wr * 32 + mt * 16 + (lane & 15);
            const int acol = (lane >> 4) * 8;
            uint32_t pa[8][4];
#pragma unroll
            for (int ks = 0; ks < 8; ks++)
                ldm_x4(pa[ks], sb + PSH_B + (uint32_t)(arow * 136 + ks * 16 + acol) * 2);

            const int vrow_in = lane & 15;
#pragma unroll
            for (int nt = 0; nt < 4; nt++) {
                const int vcol = wc * 32 + nt * 8;
#pragma unroll
                for (int ks = 0; ks < 8; ks++) {
                    uint32_t vb[2];
                    ldm_x2t(vb, sb + VSH_B + (uint32_t)((ks * 16 + vrow_in) * 72 + vcol) * 2);
                    mma16(oacc[mt][nt], pa[ks], vb);
                }
            }
        }
        __syncthreads();
    }

    // ---- row-sum reduction ----
#pragma unroll
    for (int mt = 0; mt < 2; mt++)
#pragma unroll
        for (int j = 0; j < 2; j++) {
            float v = part[mt][j];
            v += __shfl_xor_sync(0xffffffffu, v, 1);
            v += __shfl_xor_sync(0xffffffffu, v, 2);
            if (k4 == 0)
                atomicAdd(&Ls[wr * 32 + mt * 16 + j * 8 + g], v);
        }
    __syncthreads();

    // ---- normalize + store ----
#pragma unroll
    for (int mt = 0; mt < 2; mt++) {
        const int rl = wr * 32 + mt * 16 + g;
        const float inv0 = 1.f / Ls[rl];
        const float inv1 = 1.f / Ls[rl + 8];
        float* Ob = g_A + ((size_t)(b * SEQ + qt * 128 + rl)) * HIDDEN + h * HDIM;
#pragma unroll
        for (int nt = 0; nt < 4; nt++) {
            int c = wc * 32 + nt * 8 + 2 * k4;
            float2 v0 = { oacc[mt][nt][0] * inv0, oacc[mt][nt][1] * inv0 };
            float2 v1 = { oacc[mt][nt][2] * inv1, oacc[mt][nt][3] * inv1 };
            *(float2*)(Ob + c) = v0;
            *(float2*)(Ob + (size_t)8 * HIDDEN + c) = v1;
        }
    }
}

// ---------------- launch --------------------------------------------------
extern "C" void kernel_launch(void* const* d_in, const int* in_sizes, int n_in,
                              void* d_out, int out_size)
{
    const float* X    = (const float*)d_in[0];
    const float* Wq   = (const float*)d_in[1];
    const float* bq   = (const float*)d_in[2];
    const float* Wk   = (const float*)d_in[3];
    const float* bk   = (const float*)d_in[4];
    const float* Wv   = (const float*)d_in[5];
    const float* bv   = (const float*)d_in[6];
    const float* Wo   = (const float*)d_in[7];
    const float* bo   = (const float*)d_in[8];
    const int*   mask = (const int*)d_in[9];
    float* out = (float*)d_out;

    float *qp = nullptr, *ap = nullptr;
    cudaGetSymbolAddress((void**)&qp, g_Q);
    cudaGetSymbolAddress((void**)&ap, g_A);

    cudaFuncSetAttribute(gemm_mma, cudaFuncAttributeMaxDynamicSharedMemorySize, G_SMEM);
    cudaFuncSetAttribute(attn_mma, cudaFuncAttributeMaxDynamicSharedMemorySize, ATT_SMEM);

    // 1) QKV: 8 Q col-tiles + 1 combined [K|V] tile
    dim3 g1(9, MTOT / 128);
    gemm_mma<<<g1, 256, G_SMEM>>>(X, Wq, bq, qp, Wk, bk, Wv, bv, 8);

    // 2) attention
    dim3 g2(SEQ / 128, NHEADS, BATCH);
    attn_mma<<<g2, 256, ATT_SMEM>>>(mask);

    // 3) O projection -> d_out
    dim3 g3(HIDDEN / 128, MTOT / 128);
    gemm_mma<<<g3, 256, G_SMEM>>>(ap, Wo, bo, out, nullptr, nullptr, nullptr, nullptr, -1);
}

// round 6
// speedup vs baseline: 2.7023x; 1.6355x over previous
#include <cuda_runtime.h>
#include <cuda_fp16.h>
#include <cstdint>

#define BATCH   2
#define SEQ     2048
#define HIDDEN  1024
#define NHEADS  16
#define HDIM    64
#define MTOT    (BATCH*SEQ)
#define NQKV    1152    // 1024 Q + 64 K + 64 V

// ---------------- fp16 scratch ----------------
__device__ __align__(16) __half g_Xh  [MTOT * HIDDEN];
__device__ __align__(16) __half g_Qh  [MTOT * HIDDEN];   // pre-scaled by 1/8
__device__ __align__(16) __half g_Kh  [MTOT * HDIM];
__device__ __align__(16) __half g_Vh  [MTOT * HDIM];
__device__ __align__(16) __half g_Ah  [MTOT * HIDDEN];
__device__ __align__(16) __half g_Wqkv[HIDDEN * NQKV];
__device__ __align__(16) __half g_Woh [HIDDEN * HIDDEN];
__device__ __align__(16) float  g_bqkv[NQKV];

// ---------------- helpers ----------------
__device__ __forceinline__ uint32_t smem_u32(const void* p) {
    uint32_t a;
    asm("{ .reg .u64 t; cvta.to.shared.u64 t, %1; cvt.u32.u64 %0, t; }" : "=r"(a) : "l"(p));
    return a;
}
__device__ __forceinline__ void mma16(float* c, const uint32_t* a, const uint32_t* b) {
    asm volatile(
        "mma.sync.aligned.m16n8k16.row.col.f32.f16.f16.f32 "
        "{%0,%1,%2,%3},{%4,%5,%6,%7},{%8,%9},{%0,%1,%2,%3};"
        : "+f"(c[0]), "+f"(c[1]), "+f"(c[2]), "+f"(c[3])
        : "r"(a[0]), "r"(a[1]), "r"(a[2]), "r"(a[3]), "r"(b[0]), "r"(b[1]));
}
__device__ __forceinline__ void ldm_x4(uint32_t* r, uint32_t a) {
    asm volatile("ldmatrix.sync.aligned.m8n8.x4.shared.b16 {%0,%1,%2,%3}, [%4];"
        : "=r"(r[0]), "=r"(r[1]), "=r"(r[2]), "=r"(r[3]) : "r"(a));
}
__device__ __forceinline__ void ldm_x4t(uint32_t* r, uint32_t a) {
    asm volatile("ldmatrix.sync.aligned.m8n8.x4.trans.shared.b16 {%0,%1,%2,%3}, [%4];"
        : "=r"(r[0]), "=r"(r[1]), "=r"(r[2]), "=r"(r[3]) : "r"(a));
}
__device__ __forceinline__ void ldm_x2(uint32_t* r, uint32_t a) {
    asm volatile("ldmatrix.sync.aligned.m8n8.x2.shared.b16 {%0,%1}, [%2];"
        : "=r"(r[0]), "=r"(r[1]) : "r"(a));
}
__device__ __forceinline__ void ldm_x2t(uint32_t* r, uint32_t a) {
    asm volatile("ldmatrix.sync.aligned.m8n8.x2.trans.shared.b16 {%0,%1}, [%2];"
        : "=r"(r[0]), "=r"(r[1]) : "r"(a));
}
#define CP_A16(dst, src) \
    asm volatile("cp.async.cg.shared.global [%0], [%1], 16;" :: "r"(dst), "l"(src) : "memory")
#define CP_COMMIT() asm volatile("cp.async.commit_group;" ::: "memory")
#define CP_WAIT0()  asm volatile("cp.async.wait_group 0;" ::: "memory")
#define CP_WAIT1()  asm volatile("cp.async.wait_group 1;" ::: "memory")

// ============ convert: fp32 inputs -> fp16 scratch (once per launch) =========
__global__ __launch_bounds__(256)
void conv_kernel(const float* __restrict__ X,
                 const float* __restrict__ Wq, const float* __restrict__ bq,
                 const float* __restrict__ Wk, const float* __restrict__ bk,
                 const float* __restrict__ Wv, const float* __restrict__ bv,
                 const float* __restrict__ Wo)
{
    int idx = blockIdx.x * 256 + threadIdx.x;
    if (idx < 1048576) {
        float4 v = ((const float4*)X)[idx];
        *(__half2*)&g_Xh[idx * 4]     = __floats2half2_rn(v.x, v.y);
        *(__half2*)&g_Xh[idx * 4 + 2] = __floats2half2_rn(v.z, v.w);
    } else if (idx < 1310720) {
        int i = idx - 1048576;
        float4 v = ((const float4*)Wo)[i];
        *(__half2*)&g_Woh[i * 4]     = __floats2half2_rn(v.x, v.y);
        *(__half2*)&g_Woh[i * 4 + 2] = __floats2half2_rn(v.z, v.w);
    } else if (idx < 1605632) {
        int u = idx - 1310720;
        int row = u / 288, c = (u % 288) * 4;
        float4 v;
        if (c < 1024)      v = *(const float4*)(Wq + row * 1024 + c);
        else if (c < 1088) v = *(const float4*)(Wk + row * 64 + c - 1024);
        else               v = *(const float4*)(Wv + row * 64 + c - 1088);
        __half* d = &g_Wqkv[row * NQKV + c];
        *(__half2*)d       = __floats2half2_rn(v.x, v.y);
        *(__half2*)(d + 2) = __floats2half2_rn(v.z, v.w);
    } else if (idx < 1605920) {
        int c = (idx - 1605632) * 4;
        float4 v;
        if (c < 1024)      v = *(const float4*)(bq + c);
        else if (c < 1088) v = *(const float4*)(bk + c - 1024);
        else               v = *(const float4*)(bv + c - 1088);
        *(float4*)&g_bqkv[c] = v;
    }
}

// ============ GEMM fp16: C = A[M,1024] @ W[1024,WN] + bias ===================
// 128x128 tile, 8 warps (2x4), K-chunk 64, cp.async double-buffered.
// mode 0: QKV -> fp16 outputs (Q scaled 1/8, K/V split). mode 1: f32 out + bias.
#define GAS0 0
#define GWS0 18432
#define GAS1 35840
#define GWS1 54272
#define GBI  71680
#define G_SMEM 72192

__global__ __launch_bounds__(256, 2)
void gemm_h(const __half* __restrict__ A, const __half* __restrict__ W, int WN,
            const float* __restrict__ bias, float* __restrict__ C, int mode)
{
    extern __shared__ char smc[];
    const uint32_t sb = smem_u32(smc);
    float* Bias = (float*)(smc + GBI);

    const int tid = threadIdx.x, lane = tid & 31, wid = tid >> 5;
    const int g = lane >> 2, k4 = lane & 3;
    const int wr = wid >> 2, wc = wid & 3;
    const int m0 = blockIdx.y * 128;
    const int n0 = blockIdx.x * 128;

    if (tid < 128) Bias[tid] = bias[n0 + tid];

    const uint32_t asb[2] = { sb + GAS0, sb + GAS1 };
    const uint32_t wsb[2] = { sb + GWS0, sb + GWS1 };

    // prologue: chunk 0
    {
#pragma unroll
        for (int l = 0; l < 4; l++) {
            int idx = tid + l * 256;
            int r = idx >> 3, c8 = idx & 7;
            CP_A16(asb[0] + (uint32_t)(r * 72 + c8 * 8) * 2,
                   (const void*)(A + (size_t)(m0 + r) * HIDDEN + c8 * 8));
        }
#pragma unroll
        for (int l = 0; l < 4; l++) {
            int idx = tid + l * 256;
            int r = idx >> 4, c8 = idx & 15;
            CP_A16(wsb[0] + (uint32_t)(r * 136 + c8 * 8) * 2,
                   (const void*)(W + (size_t)r * WN + n0 + c8 * 8));
        }
        CP_COMMIT();
    }

    float acc[4][4][4] = {};

    for (int kc = 0; kc < 16; ++kc) {
        if (kc < 15) {
            const int k0 = (kc + 1) * 64;
            const int nb = (kc + 1) & 1;
#pragma unroll
            for (int l = 0; l < 4; l++) {
                int idx = tid + l * 256;
                int r = idx >> 3, c8 = idx & 7;
                CP_A16(asb[nb] + (uint32_t)(r * 72 + c8 * 8) * 2,
                       (const void*)(A + (size_t)(m0 + r) * HIDDEN + k0 + c8 * 8));
            }
#pragma unroll
            for (int l = 0; l < 4; l++) {
                int idx = tid + l * 256;
                int r = idx >> 4, c8 = idx & 15;
                CP_A16(wsb[nb] + (uint32_t)(r * 136 + c8 * 8) * 2,
                       (const void*)(W + (size_t)(k0 + r) * WN + n0 + c8 * 8));
            }
            CP_COMMIT();
            CP_WAIT1();
        } else {
            CP_WAIT0();
        }
        __syncthreads();

        const uint32_t as = asb[kc & 1], ws = wsb[kc & 1];
#pragma unroll
        for (int ks = 0; ks < 4; ++ks) {
            uint32_t a[4][4];
#pragma unroll
            for (int mt = 0; mt < 4; mt++)
                ldm_x4(a[mt], as + (uint32_t)((wr * 64 + mt * 16 + (lane & 15)) * 72
                                              + ks * 16 + (lane >> 4) * 8) * 2);
            const int i = lane >> 3;
#pragma unroll
            for (int p = 0; p < 2; p++) {
                uint32_t b4[4];
                ldm_x4t(b4, ws + (uint32_t)((ks * 16 + (i & 1) * 8 + (lane & 7)) * 136
                                            + wc * 32 + p * 16 + (i >> 1) * 8) * 2);
#pragma unroll
                for (int mt = 0; mt < 4; mt++) {
                    mma16(acc[mt][2 * p],     a[mt], b4);
                    mma16(acc[mt][2 * p + 1], a[mt], b4 + 2);
                }
            }
        }
        __syncthreads();
    }

    // ---- epilogue ----
    const float sc = (mode == 0 && n0 < 1024) ? 0.125f : 1.0f;
#pragma unroll
    for (int mt = 0; mt < 4; mt++) {
        const int r = m0 + wr * 64 + mt * 16 + g;
#pragma unroll
        for (int nt = 0; nt < 4; nt++) {
            const int c = wc * 32 + nt * 8 + 2 * k4;
            float v00 = (acc[mt][nt][0] + Bias[c])     * sc;
            float v01 = (acc[mt][nt][1] + Bias[c + 1]) * sc;
            float v10 = (acc[mt][nt][2] + Bias[c])     * sc;
            float v11 = (acc[mt][nt][3] + Bias[c + 1]) * sc;
            if (mode == 1) {
                float2 a0 = { v00, v01 }, a1 = { v10, v11 };
                *(float2*)(C + (size_t)r * HIDDEN + n0 + c) = a0;
                *(float2*)(C + (size_t)(r + 8) * HIDDEN + n0 + c) = a1;
            } else if (n0 < 1024) {
                *(__half2*)&g_Qh[(size_t)r * HIDDEN + n0 + c]       = __floats2half2_rn(v00, v01);
                *(__half2*)&g_Qh[(size_t)(r + 8) * HIDDEN + n0 + c] = __floats2half2_rn(v10, v11);
            } else if (c < 64) {
                *(__half2*)&g_Kh[(size_t)r * HDIM + c]       = __floats2half2_rn(v00, v01);
                *(__half2*)&g_Kh[(size_t)(r + 8) * HDIM + c] = __floats2half2_rn(v10, v11);
            } else {
                *(__half2*)&g_Vh[(size_t)r * HDIM + c - 64]       = __floats2half2_rn(v00, v01);
                *(__half2*)&g_Vh[(size_t)(r + 8) * HDIM + c - 64] = __floats2half2_rn(v10, v11);
            }
        }
    }
}

// ============ attention: fp16 mma + ldmatrix + cp.async ======================
// CTA: 128 q-rows, 8 warps (4x2). Same proven round-5 shape; fp16 sources.
#define QSH_B 0
#define KSH_B 18432
#define VSH_B 36864
#define PSH_B 55296
#define MSK_B 90112
#define LS_B  90624
#define ATT_SMEM 91136

__global__ __launch_bounds__(256, 2)
void attn_h(const int* __restrict__ mask)
{
    extern __shared__ char smc[];
    const uint32_t sb = smem_u32(smc);
    __half* Psh = (__half*)(smc + PSH_B);
    int*    Msk = (int*)(smc + MSK_B);
    float*  Ls  = (float*)(smc + LS_B);

    const int tid = threadIdx.x, lane = tid & 31, wid = tid >> 5;
    const int g = lane >> 2, k4 = lane & 3;
    const int wr = wid >> 1, wc = wid & 1;
    const int qt = blockIdx.x, h = blockIdx.y, b = blockIdx.z;

    // ---- Q tile (once): pre-scaled fp16, straight cp.async copy ----
    {
        const __half* Qb = g_Qh + ((size_t)(b * SEQ + qt * 128)) * HIDDEN + h * HDIM;
#pragma unroll
        for (int l = 0; l < 4; l++) {
            int idx = tid + l * 256;
            int r = idx >> 3, c8 = idx & 7;
            CP_A16(sb + QSH_B + (uint32_t)(r * 72 + c8 * 8) * 2,
                   (const void*)(Qb + (size_t)r * HIDDEN + c8 * 8));
        }
        CP_COMMIT();
    }
    if (tid < 128) Ls[tid] = 0.f;

    float oacc[2][4][4] = {};
    float part[2][2] = {};

    const __half* Kb = g_Kh + (size_t)b * SEQ * HDIM;
    const __half* Vb = g_Vh + (size_t)b * SEQ * HDIM;
    const int*    Mb = mask + (size_t)b * SEQ;

    for (int kt = 0; kt < 16; ++kt) {
        // ---- K/V tiles via cp.async; mask via regular store ----
#pragma unroll
        for (int l = 0; l < 4; l++) {
            int idx = tid + l * 256;
            int r = idx >> 3, c8 = idx & 7;
            uint32_t off = (uint32_t)(r * 72 + c8 * 8) * 2;
            const size_t src = (size_t)(kt * 128 + r) * HDIM + c8 * 8;
            CP_A16(sb + KSH_B + off, (const void*)(Kb + src));
            CP_A16(sb + VSH_B + off, (const void*)(Vb + src));
        }
        if (tid < 128) Msk[tid] = Mb[kt * 128 + tid];
        CP_COMMIT();
        CP_WAIT0();
        __syncthreads();

        // ---- S = Q @ K^T ; warp tile 32 rows x 64 keys ----
#pragma unroll
        for (int mt = 0; mt < 2; ++mt) {
            const int arow = wr * 32 + mt * 16 + (lane & 15);
            const int acol = (lane >> 4) * 8;
            uint32_t qa[4][4];
#pragma unroll
            for (int ks = 0; ks < 4; ks++)
                ldm_x4(qa[ks], sb + QSH_B + (uint32_t)(arow * 72 + ks * 16 + acol) * 2);

            float sacc[8][4] = {};
            const int ln = lane & 15;
            const int krow_in = (ln & 7);
            const int kcol_in = (ln >> 3) * 8;
#pragma unroll
            for (int nt = 0; nt < 8; nt++) {
                const int krow = wc * 64 + nt * 8 + krow_in;
#pragma unroll
                for (int ks = 0; ks < 4; ks++) {
                    uint32_t bb[2];
                    ldm_x2(bb, sb + KSH_B + (uint32_t)(krow * 72 + ks * 16 + kcol_in) * 2);
                    mma16(sacc[nt], qa[ks], bb);
                }
            }

            // ---- P = exp(S) (masked); pack fp16; row partials ----
            const int prow = wr * 32 + mt * 16 + g;
#pragma unroll
            for (int nt = 0; nt < 8; nt++) {
                int c = wc * 64 + nt * 8 + 2 * k4;
                bool m0 = Msk[c] != 0, m1 = Msk[c + 1] != 0;
                float p00 = m0 ? __expf(sacc[nt][0]) : 0.f;
                float p01 = m1 ? __expf(sacc[nt][1]) : 0.f;
                float p10 = m0 ? __expf(sacc[nt][2]) : 0.f;
                float p11 = m1 ? __expf(sacc[nt][3]) : 0.f;
                part[mt][0] += p00 + p01;
                part[mt][1] += p10 + p11;
                *(__half2*)&Psh[prow * 136 + c]       = __floats2half2_rn(p00, p01);
                *(__half2*)&Psh[(prow + 8) * 136 + c] = __floats2half2_rn(p10, p11);
            }
        }
        __syncthreads();

        // ---- O += P @ V ; warp tile 32 rows x 32 dims, K = 128 keys ----
#pragma unroll
        for (int mt = 0; mt < 2; ++mt) {
            const int arow = wr * 32 + mt * 16 + (lane & 15);
            const int acol = (lane >> 4) * 8;
            uint32_t pa[8][4];
#pragma unroll
            for (int ks = 0; ks < 8; ks++)
                ldm_x4(pa[ks], sb + PSH_B + (uint32_t)(arow * 136 + ks * 16 + acol) * 2);

            const int vrow_in = lane & 15;
#pragma unroll
            for (int nt = 0; nt < 4; nt++) {
                const int vcol = wc * 32 + nt * 8;
#pragma unroll
                for (int ks = 0; ks < 8; ks++) {
                    uint32_t vb[2];
                    ldm_x2t(vb, sb + VSH_B + (uint32_t)((ks * 16 + vrow_in) * 72 + vcol) * 2);
                    mma16(oacc[mt][nt], pa[ks], vb);
                }
            }
        }
        __syncthreads();
    }

    // ---- row-sum reduction ----
#pragma unroll
    for (int mt = 0; mt < 2; mt++)
#pragma unroll
        for (int j = 0; j < 2; j++) {
            float v = part[mt][j];
            v += __shfl_xor_sync(0xffffffffu, v, 1);
            v += __shfl_xor_sync(0xffffffffu, v, 2);
            if (k4 == 0)
                atomicAdd(&Ls[wr * 32 + mt * 16 + j * 8 + g], v);
        }
    __syncthreads();

    // ---- normalize + store fp16 ----
#pragma unroll
    for (int mt = 0; mt < 2; mt++) {
        const int rl = wr * 32 + mt * 16 + g;
        const float inv0 = 1.f / Ls[rl];
        const float inv1 = 1.f / Ls[rl + 8];
        __half* Ob = g_Ah + ((size_t)(b * SEQ + qt * 128 + rl)) * HIDDEN + h * HDIM;
#pragma unroll
        for (int nt = 0; nt < 4; nt++) {
            int c = wc * 32 + nt * 8 + 2 * k4;
            *(__half2*)(Ob + c) = __floats2half2_rn(oacc[mt][nt][0] * inv0,
                                                    oacc[mt][nt][1] * inv0);
            *(__half2*)(Ob + (size_t)8 * HIDDEN + c) = __floats2half2_rn(oacc[mt][nt][2] * inv1,
                                                                         oacc[mt][nt][3] * inv1);
        }
    }
}

// ---------------- launch --------------------------------------------------
extern "C" void kernel_launch(void* const* d_in, const int* in_sizes, int n_in,
                              void* d_out, int out_size)
{
    const float* X    = (const float*)d_in[0];
    const float* Wq   = (const float*)d_in[1];
    const float* bq   = (const float*)d_in[2];
    const float* Wk   = (const float*)d_in[3];
    const float* bk   = (const float*)d_in[4];
    const float* Wv   = (const float*)d_in[5];
    const float* bv   = (const float*)d_in[6];
    const float* Wo   = (const float*)d_in[7];
    const float* bo   = (const float*)d_in[8];
    const int*   mask = (const int*)d_in[9];
    float* out = (float*)d_out;

    __half *xh, *ah, *wqkv, *woh;
    float* bqkv;
    cudaGetSymbolAddress((void**)&xh,   g_Xh);
    cudaGetSymbolAddress((void**)&ah,   g_Ah);
    cudaGetSymbolAddress((void**)&wqkv, g_Wqkv);
    cudaGetSymbolAddress((void**)&woh,  g_Woh);
    cudaGetSymbolAddress((void**)&bqkv, g_bqkv);

    cudaFuncSetAttribute(gemm_h, cudaFuncAttributeMaxDynamicSharedMemorySize, G_SMEM);
    cudaFuncSetAttribute(attn_h, cudaFuncAttributeMaxDynamicSharedMemorySize, ATT_SMEM);

    // 0) convert inputs to fp16 scratch
    conv_kernel<<<6274, 256>>>(X, Wq, bq, Wk, bk, Wv, bv, Wo);

    // 1) fused QKV projection (uniform GEMM over packed weights)
    dim3 g1(NQKV / 128, MTOT / 128);
    gemm_h<<<g1, 256, G_SMEM>>>(xh, wqkv, NQKV, bqkv, nullptr, 0);

    // 2) attention
    dim3 g2(SEQ / 128, NHEADS, BATCH);
    attn_h<<<g2, 256, ATT_SMEM>>>(mask);

    // 3) O projection -> d_out (f32 + bias)
    dim3 g3(HIDDEN / 128, MTOT / 128);
    gemm_h<<<g3, 256, G_SMEM>>>(ah, woh, HIDDEN, bo, out, 1);
}

// round 7
// speedup vs baseline: 2.9319x; 1.0850x over previous
#include <cuda_runtime.h>
#include <cuda_fp16.h>
#include <cstdint>

#define BATCH   2
#define SEQ     2048
#define HIDDEN  1024
#define NHEADS  16
#define HDIM    64
#define MTOT    (BATCH*SEQ)
#define NQKV    1152    // 1024 Q + 64 K + 64 V

// ---------------- fp16 scratch ----------------
__device__ __align__(16) __half g_Xh  [MTOT * HIDDEN];
__device__ __align__(16) __half g_Qh  [MTOT * HIDDEN];   // pre-scaled by 1/8
__device__ __align__(16) __half g_Kh  [MTOT * HDIM];
__device__ __align__(16) __half g_Vh  [MTOT * HDIM];
__device__ __align__(16) __half g_Ah  [MTOT * HIDDEN];
__device__ __align__(16) __half g_Wqkv[HIDDEN * NQKV];
__device__ __align__(16) __half g_Woh [HIDDEN * HIDDEN];
__device__ __align__(16) float  g_bqkv[NQKV];

// ---------------- helpers ----------------
__device__ __forceinline__ uint32_t smem_u32(const void* p) {
    uint32_t a;
    asm("{ .reg .u64 t; cvta.to.shared.u64 t, %1; cvt.u32.u64 %0, t; }" : "=r"(a) : "l"(p));
    return a;
}
__device__ __forceinline__ void mma16(float* c, const uint32_t* a, const uint32_t* b) {
    asm volatile(
        "mma.sync.aligned.m16n8k16.row.col.f32.f16.f16.f32 "
        "{%0,%1,%2,%3},{%4,%5,%6,%7},{%8,%9},{%0,%1,%2,%3};"
        : "+f"(c[0]), "+f"(c[1]), "+f"(c[2]), "+f"(c[3])
        : "r"(a[0]), "r"(a[1]), "r"(a[2]), "r"(a[3]), "r"(b[0]), "r"(b[1]));
}
__device__ __forceinline__ void ldm_x4(uint32_t* r, uint32_t a) {
    asm volatile("ldmatrix.sync.aligned.m8n8.x4.shared.b16 {%0,%1,%2,%3}, [%4];"
        : "=r"(r[0]), "=r"(r[1]), "=r"(r[2]), "=r"(r[3]) : "r"(a));
}
__device__ __forceinline__ void ldm_x4t(uint32_t* r, uint32_t a) {
    asm volatile("ldmatrix.sync.aligned.m8n8.x4.trans.shared.b16 {%0,%1,%2,%3}, [%4];"
        : "=r"(r[0]), "=r"(r[1]), "=r"(r[2]), "=r"(r[3]) : "r"(a));
}
__device__ __forceinline__ void ldm_x2(uint32_t* r, uint32_t a) {
    asm volatile("ldmatrix.sync.aligned.m8n8.x2.shared.b16 {%0,%1}, [%2];"
        : "=r"(r[0]), "=r"(r[1]) : "r"(a));
}
__device__ __forceinline__ void ldm_x2t(uint32_t* r, uint32_t a) {
    asm volatile("ldmatrix.sync.aligned.m8n8.x2.trans.shared.b16 {%0,%1}, [%2];"
        : "=r"(r[0]), "=r"(r[1]) : "r"(a));
}
__device__ __forceinline__ uint32_t packh2(float a, float b) {
    __half2 h = __floats2half2_rn(a, b);
    return *(uint32_t*)&h;
}
#define CP_A16(dst, src) \
    asm volatile("cp.async.cg.shared.global [%0], [%1], 16;" :: "r"(dst), "l"(src) : "memory")
#define CP_COMMIT() asm volatile("cp.async.commit_group;" ::: "memory")
#define CP_WAIT(n)  asm volatile("cp.async.wait_group %0;" :: "n"(n) : "memory")

// ============ convert: fp32 inputs -> fp16 scratch ===========================
__global__ __launch_bounds__(256)
void conv_kernel(const float* __restrict__ X,
                 const float* __restrict__ Wq, const float* __restrict__ bq,
                 const float* __restrict__ Wk, const float* __restrict__ bk,
                 const float* __restrict__ Wv, const float* __restrict__ bv,
                 const float* __restrict__ Wo)
{
    int idx = blockIdx.x * 256 + threadIdx.x;
    if (idx < 1048576) {
        float4 v = ((const float4*)X)[idx];
        *(__half2*)&g_Xh[idx * 4]     = __floats2half2_rn(v.x, v.y);
        *(__half2*)&g_Xh[idx * 4 + 2] = __floats2half2_rn(v.z, v.w);
    } else if (idx < 1310720) {
        int i = idx - 1048576;
        float4 v = ((const float4*)Wo)[i];
        *(__half2*)&g_Woh[i * 4]     = __floats2half2_rn(v.x, v.y);
        *(__half2*)&g_Woh[i * 4 + 2] = __floats2half2_rn(v.z, v.w);
    } else if (idx < 1605632) {
        int u = idx - 1310720;
        int row = u / 288, c = (u % 288) * 4;
        float4 v;
        if (c < 1024)      v = *(const float4*)(Wq + row * 1024 + c);
        else if (c < 1088) v = *(const float4*)(Wk + row * 64 + c - 1024);
        else               v = *(const float4*)(Wv + row * 64 + c - 1088);
        __half* d = &g_Wqkv[row * NQKV + c];
        *(__half2*)d       = __floats2half2_rn(v.x, v.y);
        *(__half2*)(d + 2) = __floats2half2_rn(v.z, v.w);
    } else if (idx < 1605920) {
        int c = (idx - 1605632) * 4;
        float4 v;
        if (c < 1024)      v = *(const float4*)(bq + c);
        else if (c < 1088) v = *(const float4*)(bk + c - 1024);
        else               v = *(const float4*)(bv + c - 1088);
        *(float4*)&g_bqkv[c] = v;
    }
}

// ============ GEMM fp16: 128x128 tile, K-chunk 32, 4-stage cp.async ==========
#define GSTA 10240            // 128*40*2
#define GSTW 8704             // 32*136*2
#define GW_B 40960            // 4*GSTA
#define GBI_B 75776           // GW_B + 4*GSTW
#define G_SMEM 76288

__device__ __forceinline__ void g_issue(uint32_t sb, int buf, int k0, int tid,
                                        const __half* A, const __half* W,
                                        int WN, int m0, int n0)
{
    const uint32_t as = sb + buf * GSTA;
    const uint32_t ws = sb + GW_B + buf * GSTW;
#pragma unroll
    for (int l = 0; l < 2; l++) {
        int idx = tid + l * 256;
        int r = idx >> 2, c8 = idx & 3;
        CP_A16(as + (uint32_t)(r * 40 + c8 * 8) * 2,
               (const void*)(A + (size_t)(m0 + r) * HIDDEN + k0 + c8 * 8));
    }
#pragma unroll
    for (int l = 0; l < 2; l++) {
        int idx = tid + l * 256;
        int r = idx >> 4, c8 = idx & 15;
        CP_A16(ws + (uint32_t)(r * 136 + c8 * 8) * 2,
               (const void*)(W + (size_t)(k0 + r) * WN + n0 + c8 * 8));
    }
}

__global__ __launch_bounds__(256, 2)
void gemm_h(const __half* __restrict__ A, const __half* __restrict__ W, int WN,
            const float* __restrict__ bias, float* __restrict__ C, int mode)
{
    extern __shared__ char smc[];
    const uint32_t sb = smem_u32(smc);
    float* Bias = (float*)(smc + GBI_B);

    const int tid = threadIdx.x, lane = tid & 31, wid = tid >> 5;
    const int g = lane >> 2, k4 = lane & 3;
    const int wr = wid >> 2, wc = wid & 3;
    const int m0 = blockIdx.y * 128;
    const int n0 = blockIdx.x * 128;

    if (tid < 128) Bias[tid] = bias[n0 + tid];

    // prologue: chunks 0..2
    g_issue(sb, 0, 0,  tid, A, W, WN, m0, n0); CP_COMMIT();
    g_issue(sb, 1, 32, tid, A, W, WN, m0, n0); CP_COMMIT();
    g_issue(sb, 2, 64, tid, A, W, WN, m0, n0); CP_COMMIT();

    float acc[4][4][4] = {};

    for (int kc = 0; kc < 32; ++kc) {
        if (kc < 29) {
            g_issue(sb, (kc + 3) & 3, (kc + 3) * 32, tid, A, W, WN, m0, n0);
            CP_COMMIT();
            CP_WAIT(3);
        } else if (kc == 29) CP_WAIT(2);
        else if (kc == 30)   CP_WAIT(1);
        else                 CP_WAIT(0);
        __syncthreads();

        const uint32_t as = sb + (kc & 3) * GSTA;
        const uint32_t ws = sb + GW_B + (kc & 3) * GSTW;
        const int i = lane >> 3;
#pragma unroll
        for (int ks = 0; ks < 2; ++ks) {
            uint32_t a[4][4];
#pragma unroll
            for (int mt = 0; mt < 4; mt++)
                ldm_x4(a[mt], as + (uint32_t)((wr * 64 + mt * 16 + (lane & 15)) * 40
                                              + ks * 16 + (lane >> 4) * 8) * 2);
#pragma unroll
            for (int p = 0; p < 2; p++) {
                uint32_t b4[4];
                ldm_x4t(b4, ws + (uint32_t)((ks * 16 + (i & 1) * 8 + (lane & 7)) * 136
                                            + wc * 32 + p * 16 + (i >> 1) * 8) * 2);
#pragma unroll
                for (int mt = 0; mt < 4; mt++) {
                    mma16(acc[mt][2 * p],     a[mt], b4);
                    mma16(acc[mt][2 * p + 1], a[mt], b4 + 2);
                }
            }
        }
        __syncthreads();
    }

    // ---- epilogue ----
    const float sc = (mode == 0 && n0 < 1024) ? 0.125f : 1.0f;
#pragma unroll
    for (int mt = 0; mt < 4; mt++) {
        const int r = m0 + wr * 64 + mt * 16 + g;
#pragma unroll
        for (int nt = 0; nt < 4; nt++) {
            const int c = wc * 32 + nt * 8 + 2 * k4;
            float v00 = (acc[mt][nt][0] + Bias[c])     * sc;
            float v01 = (acc[mt][nt][1] + Bias[c + 1]) * sc;
            float v10 = (acc[mt][nt][2] + Bias[c])     * sc;
            float v11 = (acc[mt][nt][3] + Bias[c + 1]) * sc;
            if (mode == 1) {
                float2 a0 = { v00, v01 }, a1 = { v10, v11 };
                *(float2*)(C + (size_t)r * HIDDEN + n0 + c) = a0;
                *(float2*)(C + (size_t)(r + 8) * HIDDEN + n0 + c) = a1;
            } else if (n0 < 1024) {
                *(__half2*)&g_Qh[(size_t)r * HIDDEN + n0 + c]       = __floats2half2_rn(v00, v01);
                *(__half2*)&g_Qh[(size_t)(r + 8) * HIDDEN + n0 + c] = __floats2half2_rn(v10, v11);
            } else if (c < 64) {
                *(__half2*)&g_Kh[(size_t)r * HDIM + c]       = __floats2half2_rn(v00, v01);
                *(__half2*)&g_Kh[(size_t)(r + 8) * HDIM + c] = __floats2half2_rn(v10, v11);
            } else {
                *(__half2*)&g_Vh[(size_t)r * HDIM + c - 64]       = __floats2half2_rn(v00, v01);
                *(__half2*)&g_Vh[(size_t)(r + 8) * HDIM + c - 64] = __floats2half2_rn(v10, v11);
            }
        }
    }
}

// ============ attention: register-resident P, double-buffered K/V ============
// CTA: 128 q-rows, 8 warps; warp = 16 rows x full 128-key tile (two 64-key
// halves: S -> exp -> PV per half). P stays in registers: packed S C-frags of
// two adjacent n8 blocks ARE the m16n8k16 A-frags for the PV mma.
#define AQ_B  0
#define AKV_B 18432           // K/V double buffer: buf*36864, V at +18432
#define AM_B  92160           // mask: 2 x 128 ints
#define ATT_SMEM 93184

__global__ __launch_bounds__(256, 2)
void attn_h(const int* __restrict__ mask)
{
    extern __shared__ char smc[];
    const uint32_t sb = smem_u32(smc);

    const int tid = threadIdx.x, lane = tid & 31, wid = tid >> 5;
    const int g = lane >> 2, k4 = lane & 3;
    const int ln = lane & 15;
    const int kcol_in = (ln >> 3) * 8;
    const int qt = blockIdx.x, h = blockIdx.y, b = blockIdx.z;

    const __half* Qb = g_Qh + ((size_t)(b * SEQ + qt * 128)) * HIDDEN + h * HDIM;
    const __half* Kb = g_Kh + (size_t)b * SEQ * HDIM;
    const __half* Vb = g_Vh + (size_t)b * SEQ * HDIM;
    const int*    Mb = mask + (size_t)b * SEQ;
    int* Msk = (int*)(smc + AM_B);

    // ---- prologue: Q tile + K/V tile 0 ----
#pragma unroll
    for (int l = 0; l < 4; l++) {
        int idx = tid + l * 256;
        int r = idx >> 3, c8 = idx & 7;
        CP_A16(sb + AQ_B + (uint32_t)(r * 72 + c8 * 8) * 2,
               (const void*)(Qb + (size_t)r * HIDDEN + c8 * 8));
    }
    CP_COMMIT();
    {
        const uint32_t kb = sb + AKV_B;
#pragma unroll
        for (int l = 0; l < 4; l++) {
            int idx = tid + l * 256;
            int r = idx >> 3, c8 = idx & 7;
            uint32_t off = (uint32_t)(r * 72 + c8 * 8) * 2;
            CP_A16(kb + off,         (const void*)(Kb + (size_t)r * HDIM + c8 * 8));
            CP_A16(kb + 18432 + off, (const void*)(Vb + (size_t)r * HDIM + c8 * 8));
        }
        if (tid < 128) Msk[tid] = Mb[tid];
        CP_COMMIT();
    }

    uint32_t qa[4][4];
    float oacc[8][4] = {};
    float part0 = 0.f, part1 = 0.f;

    for (int kt = 0; kt < 16; ++kt) {
        // issue next tile (overlaps with this tile's compute)
        if (kt < 15) {
            const uint32_t kb = sb + AKV_B + ((kt + 1) & 1) * 36864;
            const size_t base = (size_t)((kt + 1) * 128) * HDIM;
#pragma unroll
            for (int l = 0; l < 4; l++) {
                int idx = tid + l * 256;
                int r = idx >> 3, c8 = idx & 7;
                uint32_t off = (uint32_t)(r * 72 + c8 * 8) * 2;
                CP_A16(kb + off,         (const void*)(Kb + base + (size_t)r * HDIM + c8 * 8));
                CP_A16(kb + 18432 + off, (const void*)(Vb + base + (size_t)r * HDIM + c8 * 8));
            }
            if (tid < 128) Msk[((kt + 1) & 1) * 128 + tid] = Mb[(kt + 1) * 128 + tid];
            CP_COMMIT();
            CP_WAIT(1);
        } else {
            CP_WAIT(0);
        }
        __syncthreads();

        if (kt == 0) {
#pragma unroll
            for (int ks = 0; ks < 4; ks++)
                ldm_x4(qa[ks], sb + AQ_B + (uint32_t)((wid * 16 + ln) * 72
                                                      + ks * 16 + (lane >> 4) * 8) * 2);
        }

        const uint32_t ksh = sb + AKV_B + (kt & 1) * 36864;
        const uint32_t vsh = ksh + 18432;
        const int* Mw = &Msk[(kt & 1) * 128];

#pragma unroll
        for (int hf = 0; hf < 2; ++hf) {
            // ---- S = Q @ K^T over 64 keys ----
            float sacc[8][4] = {};
#pragma unroll
            for (int nt = 0; nt < 8; nt++) {
                const int krow = hf * 64 + nt * 8 + (ln & 7);
#pragma unroll
                for (int ks = 0; ks < 4; ks++) {
                    uint32_t bb[2];
                    ldm_x2(bb, ksh + (uint32_t)(krow * 72 + ks * 16 + kcol_in) * 2);
                    mma16(sacc[nt], qa[ks], bb);
                }
            }
            // ---- P = exp(S) masked; pack to half2 (registers only) ----
            uint32_t ph0[8], ph1[8];
#pragma unroll
            for (int nt = 0; nt < 8; nt++) {
                int c = hf * 64 + nt * 8 + 2 * k4;
                bool m0 = Mw[c] != 0, m1 = Mw[c + 1] != 0;
                float p00 = m0 ? __expf(sacc[nt][0]) : 0.f;
                float p01 = m1 ? __expf(sacc[nt][1]) : 0.f;
                float p10 = m0 ? __expf(sacc[nt][2]) : 0.f;
                float p11 = m1 ? __expf(sacc[nt][3]) : 0.f;
                part0 += p00 + p01;
                part1 += p10 + p11;
                ph0[nt] = packh2(p00, p01);
                ph1[nt] = packh2(p10, p11);
            }
            // ---- O += P @ V over these 64 keys (A-frags direct from ph) ----
#pragma unroll
            for (int j = 0; j < 4; j++) {
                uint32_t a[4] = { ph0[2 * j], ph1[2 * j], ph0[2 * j + 1], ph1[2 * j + 1] };
                const int vrow = hf * 64 + j * 16 + ln;
#pragma unroll
                for (int d = 0; d < 8; d++) {
                    uint32_t vb[2];
                    ldm_x2t(vb, vsh + (uint32_t)(vrow * 72 + d * 8) * 2);
                    mma16(oacc[d], a, vb);
                }
            }
        }
        __syncthreads();
    }

    // ---- row-sum quad reduction (warp-private rows) ----
    part0 += __shfl_xor_sync(0xffffffffu, part0, 1);
    part0 += __shfl_xor_sync(0xffffffffu, part0, 2);
    part1 += __shfl_xor_sync(0xffffffffu, part1, 1);
    part1 += __shfl_xor_sync(0xffffffffu, part1, 2);
    const float inv0 = 1.f / part0;
    const float inv1 = 1.f / part1;

    // ---- normalize + store fp16 ----
    __half* Ob = g_Ah + ((size_t)(b * SEQ + qt * 128 + wid * 16 + g)) * HIDDEN + h * HDIM;
#pragma unroll
    for (int d = 0; d < 8; d++) {
        int c = d * 8 + 2 * k4;
        *(__half2*)(Ob + c) = __floats2half2_rn(oacc[d][0] * inv0, oacc[d][1] * inv0);
        *(__half2*)(Ob + (size_t)8 * HIDDEN + c) = __floats2half2_rn(oacc[d][2] * inv1,
                                                                     oacc[d][3] * inv1);
    }
}

// ---------------- launch --------------------------------------------------
extern "C" void kernel_launch(void* const* d_in, const int* in_sizes, int n_in,
                              void* d_out, int out_size)
{
    const float* X    = (const float*)d_in[0];
    const float* Wq   = (const float*)d_in[1];
    const float* bq   = (const float*)d_in[2];
    const float* Wk   = (const float*)d_in[3];
    const float* bk   = (const float*)d_in[4];
    const float* Wv   = (const float*)d_in[5];
    const float* bv   = (const float*)d_in[6];
    const float* Wo   = (const float*)d_in[7];
    const float* bo   = (const float*)d_in[8];
    const int*   mask = (const int*)d_in[9];
    float* out = (float*)d_out;

    __half *xh, *ah, *wqkv, *woh;
    float* bqkv;
    cudaGetSymbolAddress((void**)&xh,   g_Xh);
    cudaGetSymbolAddress((void**)&ah,   g_Ah);
    cudaGetSymbolAddress((void**)&wqkv, g_Wqkv);
    cudaGetSymbolAddress((void**)&woh,  g_Woh);
    cudaGetSymbolAddress((void**)&bqkv, g_bqkv);

    cudaFuncSetAttribute(gemm_h, cudaFuncAttributeMaxDynamicSharedMemorySize, G_SMEM);
    cudaFuncSetAttribute(attn_h, cudaFuncAttributeMaxDynamicSharedMemorySize, ATT_SMEM);

    // 0) convert inputs to fp16 scratch
    conv_kernel<<<6274, 256>>>(X, Wq, bq, Wk, bk, Wv, bv, Wo);

    // 1) fused QKV projection
    dim3 g1(NQKV / 128, MTOT / 128);
    gemm_h<<<g1, 256, G_SMEM>>>(xh, wqkv, NQKV, bqkv, nullptr, 0);

    // 2) attention
    dim3 g2(SEQ / 128, NHEADS, BATCH);
    attn_h<<<g2, 256, ATT_SMEM>>>(mask);

    // 3) O projection -> d_out (f32 + bias)
    dim3 g3(HIDDEN / 128, MTOT / 128);
    gemm_h<<<g3, 256, G_SMEM>>>(ah, woh, HIDDEN, bo, out, 1);
}

// round 8
// speedup vs baseline: 3.0614x; 1.0441x over previous
#include <cuda_runtime.h>
#include <cuda_fp16.h>
#include <cstdint>

#define BATCH   2
#define SEQ     2048
#define HIDDEN  1024
#define NHEADS  16
#define HDIM    64
#define MTOT    (BATCH*SEQ)
#define NQKV    1152    // 1024 Q + 64 K + 64 V

// ---------------- fp16 scratch ----------------
__device__ __align__(16) __half g_Xh  [MTOT * HIDDEN];
__device__ __align__(16) __half g_Qh  [MTOT * HIDDEN];   // pre-scaled by 1/8
__device__ __align__(16) __half g_Kh  [MTOT * HDIM];
__device__ __align__(16) __half g_Vh  [MTOT * HDIM];
__device__ __align__(16) __half g_Ah  [MTOT * HIDDEN];
__device__ __align__(16) __half g_Wqkv[HIDDEN * NQKV];
__device__ __align__(16) __half g_Woh [HIDDEN * HIDDEN];
__device__ __align__(16) float  g_bqkv[NQKV];

// ---------------- helpers ----------------
__device__ __forceinline__ uint32_t smem_u32(const void* p) {
    uint32_t a;
    asm("{ .reg .u64 t; cvta.to.shared.u64 t, %1; cvt.u32.u64 %0, t; }" : "=r"(a) : "l"(p));
    return a;
}
__device__ __forceinline__ void mma16(float* c, const uint32_t* a, const uint32_t* b) {
    asm volatile(
        "mma.sync.aligned.m16n8k16.row.col.f32.f16.f16.f32 "
        "{%0,%1,%2,%3},{%4,%5,%6,%7},{%8,%9},{%0,%1,%2,%3};"
        : "+f"(c[0]), "+f"(c[1]), "+f"(c[2]), "+f"(c[3])
        : "r"(a[0]), "r"(a[1]), "r"(a[2]), "r"(a[3]), "r"(b[0]), "r"(b[1]));
}
__device__ __forceinline__ void ldm_x4(uint32_t* r, uint32_t a) {
    asm volatile("ldmatrix.sync.aligned.m8n8.x4.shared.b16 {%0,%1,%2,%3}, [%4];"
        : "=r"(r[0]), "=r"(r[1]), "=r"(r[2]), "=r"(r[3]) : "r"(a));
}
__device__ __forceinline__ void ldm_x4t(uint32_t* r, uint32_t a) {
    asm volatile("ldmatrix.sync.aligned.m8n8.x4.trans.shared.b16 {%0,%1,%2,%3}, [%4];"
        : "=r"(r[0]), "=r"(r[1]), "=r"(r[2]), "=r"(r[3]) : "r"(a));
}
__device__ __forceinline__ uint32_t packh2(float a, float b) {
    __half2 h = __floats2half2_rn(a, b);
    return *(uint32_t*)&h;
}
#define CP_A16(dst, src) \
    asm volatile("cp.async.cg.shared.global [%0], [%1], 16;" :: "r"(dst), "l"(src) : "memory")
#define CP_COMMIT() asm volatile("cp.async.commit_group;" ::: "memory")
#define CP_WAIT(n)  asm volatile("cp.async.wait_group %0;" :: "n"(n) : "memory")

// ============ convert: fp32 inputs -> fp16 scratch ===========================
__global__ __launch_bounds__(256)
void conv_kernel(const float* __restrict__ X,
                 const float* __restrict__ Wq, const float* __restrict__ bq,
                 const float* __restrict__ Wk, const float* __restrict__ bk,
                 const float* __restrict__ Wv, const float* __restrict__ bv,
                 const float* __restrict__ Wo)
{
    int idx = blockIdx.x * 256 + threadIdx.x;
    if (idx < 1048576) {
        float4 v = ((const float4*)X)[idx];
        *(__half2*)&g_Xh[idx * 4]     = __floats2half2_rn(v.x, v.y);
        *(__half2*)&g_Xh[idx * 4 + 2] = __floats2half2_rn(v.z, v.w);
    } else if (idx < 1310720) {
        int i = idx - 1048576;
        float4 v = ((const float4*)Wo)[i];
        *(__half2*)&g_Woh[i * 4]     = __floats2half2_rn(v.x, v.y);
        *(__half2*)&g_Woh[i * 4 + 2] = __floats2half2_rn(v.z, v.w);
    } else if (idx < 1605632) {
        int u = idx - 1310720;
        int row = u / 288, c = (u % 288) * 4;
        float4 v;
        if (c < 1024)      v = *(const float4*)(Wq + row * 1024 + c);
        else if (c < 1088) v = *(const float4*)(Wk + row * 64 + c - 1024);
        else               v = *(const float4*)(Wv + row * 64 + c - 1088);
        __half* d = &g_Wqkv[row * NQKV + c];
        *(__half2*)d       = __floats2half2_rn(v.x, v.y);
        *(__half2*)(d + 2) = __floats2half2_rn(v.z, v.w);
    } else if (idx < 1605920) {
        int c = (idx - 1605632) * 4;
        float4 v;
        if (c < 1024)      v = *(const float4*)(bq + c);
        else if (c < 1088) v = *(const float4*)(bk + c - 1024);
        else               v = *(const float4*)(bv + c - 1088);
        *(float4*)&g_bqkv[c] = v;
    }
}

// ============ GEMM fp16: 128x128 tile, K-chunk 32, 4-stage cp.async ==========
// Single __syncthreads per iteration: wait -> sync -> issue(kc+3) -> compute.
#define GSTA 10240            // 128*40*2
#define GSTW 8704             // 32*136*2
#define GW_B 40960            // 4*GSTA
#define GBI_B 75776           // GW_B + 4*GSTW
#define G_SMEM 76288

__device__ __forceinline__ void g_issue(uint32_t sb, int buf, int k0, int tid,
                                        const __half* A, const __half* W,
                                        int WN, int m0, int n0)
{
    const uint32_t as = sb + buf * GSTA;
    const uint32_t ws = sb + GW_B + buf * GSTW;
#pragma unroll
    for (int l = 0; l < 2; l++) {
        int idx = tid + l * 256;
        int r = idx >> 2, c8 = idx & 3;
        CP_A16(as + (uint32_t)(r * 40 + c8 * 8) * 2,
               (const void*)(A + (size_t)(m0 + r) * HIDDEN + k0 + c8 * 8));
    }
#pragma unroll
    for (int l = 0; l < 2; l++) {
        int idx = tid + l * 256;
        int r = idx >> 4, c8 = idx & 15;
        CP_A16(ws + (uint32_t)(r * 136 + c8 * 8) * 2,
               (const void*)(W + (size_t)(k0 + r) * WN + n0 + c8 * 8));
    }
}

__global__ __launch_bounds__(256, 2)
void gemm_h(const __half* __restrict__ A, const __half* __restrict__ W, int WN,
            const float* __restrict__ bias, float* __restrict__ C, int mode)
{
    extern __shared__ char smc[];
    const uint32_t sb = smem_u32(smc);
    float* Bias = (float*)(smc + GBI_B);

    const int tid = threadIdx.x, lane = tid & 31, wid = tid >> 5;
    const int g = lane >> 2, k4 = lane & 3;
    const int wr = wid >> 2, wc = wid & 3;
    const int m0 = blockIdx.y * 128;
    const int n0 = blockIdx.x * 128;

    if (tid < 128) Bias[tid] = bias[n0 + tid];

    // prologue: chunks 0..2
    g_issue(sb, 0, 0,  tid, A, W, WN, m0, n0); CP_COMMIT();
    g_issue(sb, 1, 32, tid, A, W, WN, m0, n0); CP_COMMIT();
    g_issue(sb, 2, 64, tid, A, W, WN, m0, n0); CP_COMMIT();

    float acc[4][4][4] = {};

    for (int kc = 0; kc < 32; ++kc) {
        if (kc <= 29)      CP_WAIT(2);
        else if (kc == 30) CP_WAIT(1);
        else               CP_WAIT(0);
        __syncthreads();

        // issue next chunk AFTER the barrier: its buffer (kc-1)&3 is free,
        // and the copy overlaps this iteration's compute.
        if (kc < 29) {
            g_issue(sb, (kc + 3) & 3, (kc + 3) * 32, tid, A, W, WN, m0, n0);
            CP_COMMIT();
        }

        const uint32_t as = sb + (kc & 3) * GSTA;
        const uint32_t ws = sb + GW_B + (kc & 3) * GSTW;
        const int i = lane >> 3;
#pragma unroll
        for (int ks = 0; ks < 2; ++ks) {
            uint32_t a[4][4];
#pragma unroll
            for (int mt = 0; mt < 4; mt++)
                ldm_x4(a[mt], as + (uint32_t)((wr * 64 + mt * 16 + (lane & 15)) * 40
                                              + ks * 16 + (lane >> 4) * 8) * 2);
#pragma unroll
            for (int p = 0; p < 2; p++) {
                uint32_t b4[4];
                ldm_x4t(b4, ws + (uint32_t)((ks * 16 + (i & 1) * 8 + (lane & 7)) * 136
                                            + wc * 32 + p * 16 + (i >> 1) * 8) * 2);
#pragma unroll
                for (int mt = 0; mt < 4; mt++) {
                    mma16(acc[mt][2 * p],     a[mt], b4);
                    mma16(acc[mt][2 * p + 1], a[mt], b4 + 2);
                }
            }
        }
    }

    // ---- epilogue ----
    const float sc = (mode == 0 && n0 < 1024) ? 0.125f : 1.0f;
#pragma unroll
    for (int mt = 0; mt < 4; mt++) {
        const int r = m0 + wr * 64 + mt * 16 + g;
#pragma unroll
        for (int nt = 0; nt < 4; nt++) {
            const int c = wc * 32 + nt * 8 + 2 * k4;
            float v00 = (acc[mt][nt][0] + Bias[c])     * sc;
            float v01 = (acc[mt][nt][1] + Bias[c + 1]) * sc;
            float v10 = (acc[mt][nt][2] + Bias[c])     * sc;
            float v11 = (acc[mt][nt][3] + Bias[c + 1]) * sc;
            if (mode == 1) {
                float2 a0 = { v00, v01 }, a1 = { v10, v11 };
                *(float2*)(C + (size_t)r * HIDDEN + n0 + c) = a0;
                *(float2*)(C + (size_t)(r + 8) * HIDDEN + n0 + c) = a1;
            } else if (n0 < 1024) {
                *(__half2*)&g_Qh[(size_t)r * HIDDEN + n0 + c]       = __floats2half2_rn(v00, v01);
                *(__half2*)&g_Qh[(size_t)(r + 8) * HIDDEN + n0 + c] = __floats2half2_rn(v10, v11);
            } else if (c < 64) {
                *(__half2*)&g_Kh[(size_t)r * HDIM + c]       = __floats2half2_rn(v00, v01);
                *(__half2*)&g_Kh[(size_t)(r + 8) * HDIM + c] = __floats2half2_rn(v10, v11);
            } else {
                *(__half2*)&g_Vh[(size_t)r * HDIM + c - 64]       = __floats2half2_rn(v00, v01);
                *(__half2*)&g_Vh[(size_t)(r + 8) * HDIM + c - 64] = __floats2half2_rn(v10, v11);
            }
        }
    }
}

// ============ attention: register-resident P, 1 barrier/tile, wide LDSM ======
#define AQ_B  0
#define AKV_B 18432           // K/V double buffer: buf*36864, V at +18432
#define AM_B  92160           // mask: 2 x 128 ints
#define ATT_SMEM 93184

__global__ __launch_bounds__(256, 2)
void attn_h(const int* __restrict__ mask)
{
    extern __shared__ char smc[];
    const uint32_t sb = smem_u32(smc);

    const int tid = threadIdx.x, lane = tid & 31, wid = tid >> 5;
    const int g = lane >> 2, k4 = lane & 3;
    const int ln = lane & 15;
    const int qt = blockIdx.x, h = blockIdx.y, b = blockIdx.z;

    const __half* Qb = g_Qh + ((size_t)(b * SEQ + qt * 128)) * HIDDEN + h * HDIM;
    const __half* Kb = g_Kh + (size_t)b * SEQ * HDIM;
    const __half* Vb = g_Vh + (size_t)b * SEQ * HDIM;
    const int*    Mb = mask + (size_t)b * SEQ;
    int* Msk = (int*)(smc + AM_B);

    // ---- prologue: Q tile + K/V tile 0 (one group) ----
#pragma unroll
    for (int l = 0; l < 4; l++) {
        int idx = tid + l * 256;
        int r = idx >> 3, c8 = idx & 7;
        CP_A16(sb + AQ_B + (uint32_t)(r * 72 + c8 * 8) * 2,
               (const void*)(Qb + (size_t)r * HIDDEN + c8 * 8));
    }
    {
        const uint32_t kb = sb + AKV_B;
#pragma unroll
        for (int l = 0; l < 4; l++) {
            int idx = tid + l * 256;
            int r = idx >> 3, c8 = idx & 7;
            uint32_t off = (uint32_t)(r * 72 + c8 * 8) * 2;
            CP_A16(kb + off,         (const void*)(Kb + (size_t)r * HDIM + c8 * 8));
            CP_A16(kb + 18432 + off, (const void*)(Vb + (size_t)r * HDIM + c8 * 8));
        }
        if (tid < 128) Msk[tid] = Mb[tid];
        CP_COMMIT();
    }
    CP_WAIT(0);
    __syncthreads();

    // Q fragments once
    uint32_t qa[4][4];
#pragma unroll
    for (int ks = 0; ks < 4; ks++)
        ldm_x4(qa[ks], sb + AQ_B + (uint32_t)((wid * 16 + ln) * 72
                                              + ks * 16 + (lane >> 4) * 8) * 2);

    float oacc[8][4] = {};
    float part0 = 0.f, part1 = 0.f;

    for (int kt = 0; kt < 16; ++kt) {
        if (kt > 0) {
            CP_WAIT(0);
            __syncthreads();
        }
        // issue next tile AFTER the barrier (overlaps this tile's compute)
        if (kt < 15) {
            const uint32_t kb = sb + AKV_B + ((kt + 1) & 1) * 36864;
            const size_t base = (size_t)((kt + 1) * 128) * HDIM;
#pragma unroll
            for (int l = 0; l < 4; l++) {
                int idx = tid + l * 256;
                int r = idx >> 3, c8 = idx & 7;
                uint32_t off = (uint32_t)(r * 72 + c8 * 8) * 2;
                CP_A16(kb + off,         (const void*)(Kb + base + (size_t)r * HDIM + c8 * 8));
                CP_A16(kb + 18432 + off, (const void*)(Vb + base + (size_t)r * HDIM + c8 * 8));
            }
            if (tid < 128) Msk[((kt + 1) & 1) * 128 + tid] = Mb[(kt + 1) * 128 + tid];
            CP_COMMIT();
        }

        const uint32_t ksh = sb + AKV_B + (kt & 1) * 36864;
        const uint32_t vsh = ksh + 18432;
        const int* Mw = &Msk[(kt & 1) * 128];

#pragma unroll
        for (int hf = 0; hf < 2; ++hf) {
            // ---- S = Q @ K^T over 64 keys; K frags via x4 (2 ksteps/instr) --
            float sacc[8][4] = {};
#pragma unroll
            for (int nt = 0; nt < 8; nt++) {
                const int krow = hf * 64 + nt * 8 + (lane & 7);
#pragma unroll
                for (int ks2 = 0; ks2 < 2; ks2++) {
                    uint32_t kb4[4];
                    ldm_x4(kb4, ksh + (uint32_t)(krow * 72 + ks2 * 32 + (lane >> 3) * 8) * 2);
                    mma16(sacc[nt], qa[2 * ks2],     kb4);
                    mma16(sacc[nt], qa[2 * ks2 + 1], kb4 + 2);
                }
            }
            // ---- P = exp(S) masked; pack to half2 (registers only) ----
            uint32_t ph0[8], ph1[8];
#pragma unroll
            for (int nt = 0; nt < 8; nt++) {
                int c = hf * 64 + nt * 8 + 2 * k4;
                bool m0 = Mw[c] != 0, m1 = Mw[c + 1] != 0;
                float p00 = m0 ? __expf(sacc[nt][0]) : 0.f;
                float p01 = m1 ? __expf(sacc[nt][1]) : 0.f;
                float p10 = m0 ? __expf(sacc[nt][2]) : 0.f;
                float p11 = m1 ? __expf(sacc[nt][3]) : 0.f;
                part0 += p00 + p01;
                part1 += p10 + p11;
                ph0[nt] = packh2(p00, p01);
                ph1[nt] = packh2(p10, p11);
            }
            // ---- O += P @ V; V frags via x4t (2 dim-blocks/instr) ----
#pragma unroll
            for (int j = 0; j < 4; j++) {
                uint32_t a[4] = { ph0[2 * j], ph1[2 * j], ph0[2 * j + 1], ph1[2 * j + 1] };
                const int vrow = hf * 64 + j * 16 + ln;
#pragma unroll
                for (int d2 = 0; d2 < 4; d2++) {
                    uint32_t vb4[4];
                    ldm_x4t(vb4, vsh + (uint32_t)(vrow * 72 + d2 * 16 + (lane >> 4) * 8) * 2);
                    mma16(oacc[2 * d2],     a, vb4);
                    mma16(oacc[2 * d2 + 1], a, vb4 + 2);
                }
            }
        }
    }

    // ---- row-sum quad reduction (warp-private rows) ----
    part0 += __shfl_xor_sync(0xffffffffu, part0, 1);
    part0 += __shfl_xor_sync(0xffffffffu, part0, 2);
    part1 += __shfl_xor_sync(0xffffffffu, part1, 1);
    part1 += __shfl_xor_sync(0xffffffffu, part1, 2);
    const float inv0 = 1.f / part0;
    const float inv1 = 1.f / part1;

    // ---- normalize + store fp16 ----
    __half* Ob = g_Ah + ((size_t)(b * SEQ + qt * 128 + wid * 16 + g)) * HIDDEN + h * HDIM;
#pragma unroll
    for (int d = 0; d < 8; d++) {
        int c = d * 8 + 2 * k4;
        *(__half2*)(Ob + c) = __floats2half2_rn(oacc[d][0] * inv0, oacc[d][1] * inv0);
        *(__half2*)(Ob + (size_t)8 * HIDDEN + c) = __floats2half2_rn(oacc[d][2] * inv1,
                                                                     oacc[d][3] * inv1);
    }
}

// ---------------- launch --------------------------------------------------
extern "C" void kernel_launch(void* const* d_in, const int* in_sizes, int n_in,
                              void* d_out, int out_size)
{
    const float* X    = (const float*)d_in[0];
    const float* Wq   = (const float*)d_in[1];
    const float* bq   = (const float*)d_in[2];
    const float* Wk   = (const float*)d_in[3];
    const float* bk   = (const float*)d_in[4];
    const float* Wv   = (const float*)d_in[5];
    const float* bv   = (const float*)d_in[6];
    const float* Wo   = (const float*)d_in[7];
    const float* bo   = (const float*)d_in[8];
    const int*   mask = (const int*)d_in[9];
    float* out = (float*)d_out;

    __half *xh, *ah, *wqkv, *woh;
    float* bqkv;
    cudaGetSymbolAddress((void**)&xh,   g_Xh);
    cudaGetSymbolAddress((void**)&ah,   g_Ah);
    cudaGetSymbolAddress((void**)&wqkv, g_Wqkv);
    cudaGetSymbolAddress((void**)&woh,  g_Woh);
    cudaGetSymbolAddress((void**)&bqkv, g_bqkv);

    cudaFuncSetAttribute(gemm_h, cudaFuncAttributeMaxDynamicSharedMemorySize, G_SMEM);
    cudaFuncSetAttribute(attn_h, cudaFuncAttributeMaxDynamicSharedMemorySize, ATT_SMEM);

    // 0) convert inputs to fp16 scratch
    conv_kernel<<<6274, 256>>>(X, Wq, bq, Wk, bk, Wv, bv, Wo);

    // 1) fused QKV projection
    dim3 g1(NQKV / 128, MTOT / 128);
    gemm_h<<<g1, 256, G_SMEM>>>(xh, wqkv, NQKV, bqkv, nullptr, 0);

    // 2) attention
    dim3 g2(SEQ / 128, NHEADS, BATCH);
    attn_h<<<g2, 256, ATT_SMEM>>>(mask);

    // 3) O projection -> d_out (f32 + bias)
    dim3 g3(HIDDEN / 128, MTOT / 128);
    gemm_h<<<g3, 256, G_SMEM>>>(ah, woh, HIDDEN, bo, out, 1);
}

// round 9
// speedup vs baseline: 3.5653x; 1.1646x over previous
#include <cuda_runtime.h>
#include <cuda_fp16.h>
#include <cstdint>

#define BATCH   2
#define SEQ     2048
#define HIDDEN  1024
#define NHEADS  16
#define HDIM    64
#define MTOT    (BATCH*SEQ)
#define NQKV    1152    // 1024 Q + 64 K + 64 V

// ---------------- fp16 scratch ----------------
__device__ __align__(16) __half g_Xh  [MTOT * HIDDEN];
__device__ __align__(16) __half g_Qh  [MTOT * HIDDEN];   // pre-scaled by log2e/8
__device__ __align__(16) __half g_Kh  [MTOT * HDIM];
__device__ __align__(16) __half g_Vh  [MTOT * HDIM];
__device__ __align__(16) __half g_Ah  [MTOT * HIDDEN];
__device__ __align__(16) __half g_Wqkv[HIDDEN * NQKV];
__device__ __align__(16) __half g_Woh [HIDDEN * HIDDEN];
__device__ __align__(16) float  g_bqkv[NQKV];

// ---------------- helpers ----------------
__device__ __forceinline__ uint32_t smem_u32(const void* p) {
    uint32_t a;
    asm("{ .reg .u64 t; cvta.to.shared.u64 t, %1; cvt.u32.u64 %0, t; }" : "=r"(a) : "l"(p));
    return a;
}
__device__ __forceinline__ void mma16(float* c, const uint32_t* a, const uint32_t* b) {
    asm volatile(
        "mma.sync.aligned.m16n8k16.row.col.f32.f16.f16.f32 "
        "{%0,%1,%2,%3},{%4,%5,%6,%7},{%8,%9},{%0,%1,%2,%3};"
        : "+f"(c[0]), "+f"(c[1]), "+f"(c[2]), "+f"(c[3])
        : "r"(a[0]), "r"(a[1]), "r"(a[2]), "r"(a[3]), "r"(b[0]), "r"(b[1]));
}
__device__ __forceinline__ void ldm_x4(uint32_t* r, uint32_t a) {
    asm volatile("ldmatrix.sync.aligned.m8n8.x4.shared.b16 {%0,%1,%2,%3}, [%4];"
        : "=r"(r[0]), "=r"(r[1]), "=r"(r[2]), "=r"(r[3]) : "r"(a));
}
__device__ __forceinline__ void ldm_x4t(uint32_t* r, uint32_t a) {
    asm volatile("ldmatrix.sync.aligned.m8n8.x4.trans.shared.b16 {%0,%1,%2,%3}, [%4];"
        : "=r"(r[0]), "=r"(r[1]), "=r"(r[2]), "=r"(r[3]) : "r"(a));
}
__device__ __forceinline__ void ldm_x2t(uint32_t* r, uint32_t a) {
    asm volatile("ldmatrix.sync.aligned.m8n8.x2.trans.shared.b16 {%0,%1}, [%2];"
        : "=r"(r[0]), "=r"(r[1]) : "r"(a));
}
__device__ __forceinline__ uint32_t packh2(float a, float b) {
    __half2 h = __floats2half2_rn(a, b);
    return *(uint32_t*)&h;
}
#define CP_A16(dst, src) \
    asm volatile("cp.async.cg.shared.global [%0], [%1], 16;" :: "r"(dst), "l"(src) : "memory")
#define CP_COMMIT() asm volatile("cp.async.commit_group;" ::: "memory")
#define CP_WAIT(n)  asm volatile("cp.async.wait_group %0;" :: "n"(n) : "memory")

// ============ convert: fp32 inputs -> fp16 scratch ===========================
__global__ __launch_bounds__(256)
void conv_kernel(const float* __restrict__ X,
                 const float* __restrict__ Wq, const float* __restrict__ bq,
                 const float* __restrict__ Wk, const float* __restrict__ bk,
                 const float* __restrict__ Wv, const float* __restrict__ bv,
                 const float* __restrict__ Wo)
{
    int idx = blockIdx.x * 256 + threadIdx.x;
    if (idx < 1048576) {
        float4 v = ((const float4*)X)[idx];
        *(__half2*)&g_Xh[idx * 4]     = __floats2half2_rn(v.x, v.y);
        *(__half2*)&g_Xh[idx * 4 + 2] = __floats2half2_rn(v.z, v.w);
    } else if (idx < 1310720) {
        int i = idx - 1048576;
        float4 v = ((const float4*)Wo)[i];
        *(__half2*)&g_Woh[i * 4]     = __floats2half2_rn(v.x, v.y);
        *(__half2*)&g_Woh[i * 4 + 2] = __floats2half2_rn(v.z, v.w);
    } else if (idx < 1605632) {
        int u = idx - 1310720;
        int row = u / 288, c = (u % 288) * 4;
        float4 v;
        if (c < 1024)      v = *(const float4*)(Wq + row * 1024 + c);
        else if (c < 1088) v = *(const float4*)(Wk + row * 64 + c - 1024);
        else               v = *(const float4*)(Wv + row * 64 + c - 1088);
        __half* d = &g_Wqkv[row * NQKV + c];
        *(__half2*)d       = __floats2half2_rn(v.x, v.y);
        *(__half2*)(d + 2) = __floats2half2_rn(v.z, v.w);
    } else if (idx < 1605920) {
        int c = (idx - 1605632) * 4;
        float4 v;
        if (c < 1024)      v = *(const float4*)(bq + c);
        else if (c < 1088) v = *(const float4*)(bk + c - 1024);
        else               v = *(const float4*)(bv + c - 1088);
        *(float4*)&g_bqkv[c] = v;
    }
}

// ============ GEMM fp16: 128x128 tile, K-chunk 32, 4-stage cp.async ==========
#define GSTA 10240            // 128*40*2
#define GSTW 8704             // 32*136*2
#define GW_B 40960            // 4*GSTA
#define GBI_B 75776           // GW_B + 4*GSTW
#define G_SMEM 76288

__device__ __forceinline__ void g_issue(uint32_t sb, int buf, int k0, int tid,
                                        const __half* A, const __half* W,
                                        int WN, int m0, int n0)
{
    const uint32_t as = sb + buf * GSTA;
    const uint32_t ws = sb + GW_B + buf * GSTW;
#pragma unroll
    for (int l = 0; l < 2; l++) {
        int idx = tid + l * 256;
        int r = idx >> 2, c8 = idx & 3;
        CP_A16(as + (uint32_t)(r * 40 + c8 * 8) * 2,
               (const void*)(A + (size_t)(m0 + r) * HIDDEN + k0 + c8 * 8));
    }
#pragma unroll
    for (int l = 0; l < 2; l++) {
        int idx = tid + l * 256;
        int r = idx >> 4, c8 = idx & 15;
        CP_A16(ws + (uint32_t)(r * 136 + c8 * 8) * 2,
               (const void*)(W + (size_t)(k0 + r) * WN + n0 + c8 * 8));
    }
}

__global__ __launch_bounds__(256, 2)
void gemm_h(const __half* __restrict__ A, const __half* __restrict__ W, int WN,
            const float* __restrict__ bias, float* __restrict__ C, int mode)
{
    extern __shared__ char smc[];
    const uint32_t sb = smem_u32(smc);
    float* Bias = (float*)(smc + GBI_B);

    const int tid = threadIdx.x, lane = tid & 31, wid = tid >> 5;
    const int g = lane >> 2, k4 = lane & 3;
    const int wr = wid >> 2, wc = wid & 3;
    const int m0 = blockIdx.y * 128;
    const int n0 = blockIdx.x * 128;

    if (tid < 128) Bias[tid] = bias[n0 + tid];

    g_issue(sb, 0, 0,  tid, A, W, WN, m0, n0); CP_COMMIT();
    g_issue(sb, 1, 32, tid, A, W, WN, m0, n0); CP_COMMIT();
    g_issue(sb, 2, 64, tid, A, W, WN, m0, n0); CP_COMMIT();

    float acc[4][4][4] = {};

    for (int kc = 0; kc < 32; ++kc) {
        if (kc <= 29)      CP_WAIT(2);
        else if (kc == 30) CP_WAIT(1);
        else               CP_WAIT(0);
        __syncthreads();

        if (kc < 29) {
            g_issue(sb, (kc + 3) & 3, (kc + 3) * 32, tid, A, W, WN, m0, n0);
            CP_COMMIT();
        }

        const uint32_t as = sb + (kc & 3) * GSTA;
        const uint32_t ws = sb + GW_B + (kc & 3) * GSTW;
        const int i = lane >> 3;
#pragma unroll
        for (int ks = 0; ks < 2; ++ks) {
            uint32_t a[4][4];
#pragma unroll
            for (int mt = 0; mt < 4; mt++)
                ldm_x4(a[mt], as + (uint32_t)((wr * 64 + mt * 16 + (lane & 15)) * 40
                                              + ks * 16 + (lane >> 4) * 8) * 2);
#pragma unroll
            for (int p = 0; p < 2; p++) {
                uint32_t b4[4];
                ldm_x4t(b4, ws + (uint32_t)((ks * 16 + (i & 1) * 8 + (lane & 7)) * 136
                                            + wc * 32 + p * 16 + (i >> 1) * 8) * 2);
#pragma unroll
                for (int mt = 0; mt < 4; mt++) {
                    mma16(acc[mt][2 * p],     a[mt], b4);
                    mma16(acc[mt][2 * p + 1], a[mt], b4 + 2);
                }
            }
        }
    }

    // ---- epilogue: Q scaled by log2e/8 so softmax can use ex2 directly ----
    const float sc = (mode == 0 && n0 < 1024) ? 0.18033688f : 1.0f;
#pragma unroll
    for (int mt = 0; mt < 4; mt++) {
        const int r = m0 + wr * 64 + mt * 16 + g;
#pragma unroll
        for (int nt = 0; nt < 4; nt++) {
            const int c = wc * 32 + nt * 8 + 2 * k4;
            float v00 = (acc[mt][nt][0] + Bias[c])     * sc;
            float v01 = (acc[mt][nt][1] + Bias[c + 1]) * sc;
            float v10 = (acc[mt][nt][2] + Bias[c])     * sc;
            float v11 = (acc[mt][nt][3] + Bias[c + 1]) * sc;
            if (mode == 1) {
                float2 a0 = { v00, v01 }, a1 = { v10, v11 };
                *(float2*)(C + (size_t)r * HIDDEN + n0 + c) = a0;
                *(float2*)(C + (size_t)(r + 8) * HIDDEN + n0 + c) = a1;
            } else if (n0 < 1024) {
                *(__half2*)&g_Qh[(size_t)r * HIDDEN + n0 + c]       = __floats2half2_rn(v00, v01);
                *(__half2*)&g_Qh[(size_t)(r + 8) * HIDDEN + n0 + c] = __floats2half2_rn(v10, v11);
            } else if (c < 64) {
                *(__half2*)&g_Kh[(size_t)r * HDIM + c]       = __floats2half2_rn(v00, v01);
                *(__half2*)&g_Kh[(size_t)(r + 8) * HDIM + c] = __floats2half2_rn(v10, v11);
            } else {
                *(__half2*)&g_Vh[(size_t)r * HDIM + c - 64]       = __floats2half2_rn(v00, v01);
                *(__half2*)&g_Vh[(size_t)(r + 8) * HDIM + c - 64] = __floats2half2_rn(v10, v11);
            }
        }
    }
}

// ============ attention: ex2.f16x2 softmax, ones-column row sums =============
#define AQ_B  0
#define AKV_B 18432           // K/V double buffer: buf*36864, V at +18432
#define AM_B  92160           // mask halves: 2 x 128 x 2B
#define ATT_SMEM 92672

__global__ __launch_bounds__(256, 2)
void attn_h(const int* __restrict__ mask)
{
    extern __shared__ char smc[];
    const uint32_t sb = smem_u32(smc);

    const int tid = threadIdx.x, lane = tid & 31, wid = tid >> 5;
    const int g = lane >> 2, k4 = lane & 3;
    const int ln = lane & 15;
    const int qt = blockIdx.x, h = blockIdx.y, b = blockIdx.z;

    const __half* Qb = g_Qh + ((size_t)(b * SEQ + qt * 128)) * HIDDEN + h * HDIM;
    const __half* Kb = g_Kh + (size_t)b * SEQ * HDIM;
    const __half* Vb = g_Vh + (size_t)b * SEQ * HDIM;
    const int*    Mb = mask + (size_t)b * SEQ;
    unsigned short* MskH = (unsigned short*)(smc + AM_B);

    // ---- ones-column pad in V buffers (cols 64-71; cp.async never writes) --
    {
        const int buf = tid >> 7, r = tid & 127;
        uint4 ones = { 0x00003C00u, 0u, 0u, 0u };   // half 1.0 at col 64
        *(uint4*)(smc + AKV_B + buf * 36864 + 18432 + (r * 72 + 64) * 2) = ones;
    }

    // ---- prologue: Q tile + K/V tile 0 ----
#pragma unroll
    for (int l = 0; l < 4; l++) {
        int idx = tid + l * 256;
        int r = idx >> 3, c8 = idx & 7;
        CP_A16(sb + AQ_B + (uint32_t)(r * 72 + c8 * 8) * 2,
               (const void*)(Qb + (size_t)r * HIDDEN + c8 * 8));
    }
    {
        const uint32_t kb = sb + AKV_B;
#pragma unroll
        for (int l = 0; l < 4; l++) {
            int idx = tid + l * 256;
            int r = idx >> 3, c8 = idx & 7;
            uint32_t off = (uint32_t)(r * 72 + c8 * 8) * 2;
            CP_A16(kb + off,         (const void*)(Kb + (size_t)r * HDIM + c8 * 8));
            CP_A16(kb + 18432 + off, (const void*)(Vb + (size_t)r * HDIM + c8 * 8));
        }
        if (tid < 128) MskH[tid] = Mb[tid] ? 0x3C00 : 0;
        CP_COMMIT();
    }
    CP_WAIT(0);
    __syncthreads();

    uint32_t qa[4][4];
#pragma unroll
    for (int ks = 0; ks < 4; ks++)
        ldm_x4(qa[ks], sb + AQ_B + (uint32_t)((wid * 16 + ln) * 72
                                              + ks * 16 + (lane >> 4) * 8) * 2);

    float oacc[8][4] = {};
    float ssum[4] = {};

    for (int kt = 0; kt < 16; ++kt) {
        if (kt > 0) {
            CP_WAIT(0);
            __syncthreads();
        }
        if (kt < 15) {
            const uint32_t kb = sb + AKV_B + ((kt + 1) & 1) * 36864;
            const size_t base = (size_t)((kt + 1) * 128) * HDIM;
#pragma unroll
            for (int l = 0; l < 4; l++) {
                int idx = tid + l * 256;
                int r = idx >> 3, c8 = idx & 7;
                uint32_t off = (uint32_t)(r * 72 + c8 * 8) * 2;
                CP_A16(kb + off,         (const void*)(Kb + base + (size_t)r * HDIM + c8 * 8));
                CP_A16(kb + 18432 + off, (const void*)(Vb + base + (size_t)r * HDIM + c8 * 8));
            }
            if (tid < 128) MskH[((kt + 1) & 1) * 128 + tid] = Mb[(kt + 1) * 128 + tid] ? 0x3C00 : 0;
            CP_COMMIT();
        }

        const uint32_t ksh = sb + AKV_B + (kt & 1) * 36864;
        const uint32_t vsh = ksh + 18432;
        const unsigned short* Mw = MskH + (kt & 1) * 128;

#pragma unroll
        for (int hf = 0; hf < 2; ++hf) {
            // ---- S' = (Q*log2e/8) @ K^T over 64 keys ----
            float sacc[8][4] = {};
#pragma unroll
            for (int nt = 0; nt < 8; nt++) {
                const int krow = hf * 64 + nt * 8 + (lane & 7);
#pragma unroll
                for (int ks2 = 0; ks2 < 2; ks2++) {
                    uint32_t kb4[4];
                    ldm_x4(kb4, ksh + (uint32_t)(krow * 72 + ks2 * 32 + (lane >> 3) * 8) * 2);
                    mma16(sacc[nt], qa[2 * ks2],     kb4);
                    mma16(sacc[nt], qa[2 * ks2 + 1], kb4 + 2);
                }
            }
            // ---- P = 2^(S') via ex2.f16x2, masked by f16x2 multiply ----
            uint32_t ph0[8], ph1[8];
#pragma unroll
            for (int nt = 0; nt < 8; nt++) {
                const int c = hf * 64 + nt * 8 + 2 * k4;
                uint32_t e01 = packh2(sacc[nt][0], sacc[nt][1]);
                uint32_t e23 = packh2(sacc[nt][2], sacc[nt][3]);
                asm("ex2.approx.f16x2 %0, %1;" : "=r"(e01) : "r"(e01));
                asm("ex2.approx.f16x2 %0, %1;" : "=r"(e23) : "r"(e23));
                const uint32_t mh = *(const uint32_t*)&Mw[c];
                asm("mul.rn.f16x2 %0, %1, %2;" : "=r"(ph0[nt]) : "r"(e01), "r"(mh));
                asm("mul.rn.f16x2 %0, %1, %2;" : "=r"(ph1[nt]) : "r"(e23), "r"(mh));
            }
            // ---- O += P @ V ; ones column accumulates row sums ----
#pragma unroll
            for (int j = 0; j < 4; j++) {
                uint32_t a[4] = { ph0[2 * j], ph1[2 * j], ph0[2 * j + 1], ph1[2 * j + 1] };
                const int vrow = hf * 64 + j * 16 + ln;
                uint32_t ob[2];
                ldm_x2t(ob, vsh + (uint32_t)(vrow * 72 + 64) * 2);
                mma16(ssum, a, ob);
#pragma unroll
                for (int d2 = 0; d2 < 4; d2++) {
                    uint32_t vb4[4];
                    ldm_x4t(vb4, vsh + (uint32_t)(vrow * 72 + d2 * 16 + (lane >> 4) * 8) * 2);
                    mma16(oacc[2 * d2],     a, vb4);
                    mma16(oacc[2 * d2 + 1], a, vb4 + 2);
                }
            }
        }
    }

    // ---- row sums live in k4==0 lanes (col 64 of ones block) ----
    const float s0 = __shfl_sync(0xffffffffu, ssum[0], lane & ~3);
    const float s1 = __shfl_sync(0xffffffffu, ssum[2], lane & ~3);
    const float inv0 = 1.f / s0;
    const float inv1 = 1.f / s1;

    __half* Ob = g_Ah + ((size_t)(b * SEQ + qt * 128 + wid * 16 + g)) * HIDDEN + h * HDIM;
#pragma unroll
    for (int d = 0; d < 8; d++) {
        int c = d * 8 + 2 * k4;
        *(__half2*)(Ob + c) = __floats2half2_rn(oacc[d][0] * inv0, oacc[d][1] * inv0);
        *(__half2*)(Ob + (size_t)8 * HIDDEN + c) = __floats2half2_rn(oacc[d][2] * inv1,
                                                                     oacc[d][3] * inv1);
    }
}

// ---------------- launch --------------------------------------------------
extern "C" void kernel_launch(void* const* d_in, const int* in_sizes, int n_in,
                              void* d_out, int out_size)
{
    const float* X    = (const float*)d_in[0];
    const float* Wq   = (const float*)d_in[1];
    const float* bq   = (const float*)d_in[2];
    const float* Wk   = (const float*)d_in[3];
    const float* bk   = (const float*)d_in[4];
    const float* Wv   = (const float*)d_in[5];
    const float* bv   = (const float*)d_in[6];
    const float* Wo   = (const float*)d_in[7];
    const float* bo   = (const float*)d_in[8];
    const int*   mask = (const int*)d_in[9];
    float* out = (float*)d_out;

    __half *xh, *ah, *wqkv, *woh;
    float* bqkv;
    cudaGetSymbolAddress((void**)&xh,   g_Xh);
    cudaGetSymbolAddress((void**)&ah,   g_Ah);
    cudaGetSymbolAddress((void**)&wqkv, g_Wqkv);
    cudaGetSymbolAddress((void**)&woh,  g_Woh);
    cudaGetSymbolAddress((void**)&bqkv, g_bqkv);

    cudaFuncSetAttribute(gemm_h, cudaFuncAttributeMaxDynamicSharedMemorySize, G_SMEM);
    cudaFuncSetAttribute(attn_h, cudaFuncAttributeMaxDynamicSharedMemorySize, ATT_SMEM);

    // 0) convert inputs to fp16 scratch
    conv_kernel<<<6274, 256>>>(X, Wq, bq, Wk, bk, Wv, bv, Wo);

    // 1) fused QKV projection
    dim3 g1(NQKV / 128, MTOT / 128);
    gemm_h<<<g1, 256, G_SMEM>>>(xh, wqkv, NQKV, bqkv, nullptr, 0);

    // 2) attention
    dim3 g2(SEQ / 128, NHEADS, BATCH);
    attn_h<<<g2, 256, ATT_SMEM>>>(mask);

    // 3) O projection -> d_out (f32 + bias)
    dim3 g3(HIDDEN / 128, MTOT / 128);
    gemm_h<<<g3, 256, G_SMEM>>>(ah, woh, HIDDEN, bo, out, 1);
}